// round 9
// baseline (speedup 1.0000x reference)
#include <cuda_runtime.h>
#include <math.h>

#define Bb 4
#define Nn 128
#define Ll 20
#define Dd 512
#define SCALE 0.044194173824159216f  // 1/sqrt(512)
#define KS 8                          // split-K factor for S GEMM
#define KCH (Dd / KS)                 // 64

// ---------------- scratch (no allocations allowed) ----------------
__device__ float g_k  [Bb*Ll*Dd];        // k = f_w Wk^T + bk        [80,512]
__device__ float g_u  [Bb*Ll*Dd];        // u = k Wq                 [80,512]
__device__ float g_fbq[Bb*Nn*Dd];        // gated boundary feats     [512,512]
__device__ float g_S  [Bb*Nn*Nn];        // A_b after softmax        [4,128,128]
__device__ float g_Sp [KS*Bb*Nn*Nn];     // split-K partials of S

__device__ __forceinline__ float tanh_approx(float x) {
    float y; asm("tanh.approx.f32 %0, %1;" : "=f"(y) : "f"(x)); return y;
}

// ======== NT GEMM, BM=16 BN=32, 128 threads, double-buffered ========
__global__ void gemm_nt32(const float* __restrict__ A, const float* __restrict__ Bm,
                          const float* __restrict__ bias, float* __restrict__ C)
{
    const int K = Dd;
    int bm = blockIdx.y * 16;
    int bn = blockIdx.x * 32;

    __shared__ float Ast[2][32][18];
    __shared__ float Bst[2][32][36];

    int tid = threadIdx.x;
    int r  = tid >> 3;
    int c4 = (tid & 7) * 4;
    int brow0 = tid >> 3;
    int brow1 = brow0 + 16;

    float4 av, bv0, bv1;
    av  = *(const float4*)(A  + (long)(bm + r) * K + c4);
    bv0 = *(const float4*)(Bm + (long)(bn + brow0) * K + c4);
    bv1 = *(const float4*)(Bm + (long)(bn + brow1) * K + c4);
    Ast[0][c4+0][r]=av.x; Ast[0][c4+1][r]=av.y; Ast[0][c4+2][r]=av.z; Ast[0][c4+3][r]=av.w;
    Bst[0][c4+0][brow0]=bv0.x; Bst[0][c4+1][brow0]=bv0.y;
    Bst[0][c4+2][brow0]=bv0.z; Bst[0][c4+3][brow0]=bv0.w;
    Bst[0][c4+0][brow1]=bv1.x; Bst[0][c4+1][brow1]=bv1.y;
    Bst[0][c4+2][brow1]=bv1.z; Bst[0][c4+3][brow1]=bv1.w;
    __syncthreads();

    float a0=0.f, a1=0.f, a2=0.f, a3=0.f;
    const int nit = K / 32;
    int buf = 0;
    for (int it = 0; it < nit; it++) {
        bool more = (it + 1 < nit);
        if (more) {
            int k0n = (it + 1) * 32;
            av  = *(const float4*)(A  + (long)(bm + r) * K + k0n + c4);
            bv0 = *(const float4*)(Bm + (long)(bn + brow0) * K + k0n + c4);
            bv1 = *(const float4*)(Bm + (long)(bn + brow1) * K + k0n + c4);
        }
#pragma unroll
        for (int k = 0; k < 32; k++) {
            float a = Ast[buf][k][r];
            float4 b = *(const float4*)&Bst[buf][k][c4];
            a0 = fmaf(a, b.x, a0);
            a1 = fmaf(a, b.y, a1);
            a2 = fmaf(a, b.z, a2);
            a3 = fmaf(a, b.w, a3);
        }
        if (more) {
            int nb = buf ^ 1;
            Ast[nb][c4+0][r]=av.x; Ast[nb][c4+1][r]=av.y;
            Ast[nb][c4+2][r]=av.z; Ast[nb][c4+3][r]=av.w;
            Bst[nb][c4+0][brow0]=bv0.x; Bst[nb][c4+1][brow0]=bv0.y;
            Bst[nb][c4+2][brow0]=bv0.z; Bst[nb][c4+3][brow0]=bv0.w;
            Bst[nb][c4+0][brow1]=bv1.x; Bst[nb][c4+1][brow1]=bv1.y;
            Bst[nb][c4+2][brow1]=bv1.z; Bst[nb][c4+3][brow1]=bv1.w;
            __syncthreads();
            buf = nb;
        }
    }

    int gm = bm + r, gn = bn + c4;
    float4 bb = bias ? *(const float4*)(bias + gn) : make_float4(0.f,0.f,0.f,0.f);
    C[(long)gm * Dd + gn + 0] = a0 + bb.x;
    C[(long)gm * Dd + gn + 1] = a1 + bb.y;
    C[(long)gm * Dd + gn + 2] = a2 + bb.z;
    C[(long)gm * Dd + gn + 3] = a3 + bb.w;
}

// ======== NN GEMM, BM=16 BN=32, 128 threads, double-buffered ========
__global__ void gemm_nn32(const float* __restrict__ A, const float* __restrict__ Bm,
                          float* __restrict__ C)
{
    const int K = Dd;
    int bm = blockIdx.y * 16;
    int bn = blockIdx.x * 32;

    __shared__ float Ast[2][32][18];
    __shared__ float Bst[2][32][36];

    int tid = threadIdx.x;
    int r  = tid >> 3;
    int c4 = (tid & 7) * 4;
    int bkr0 = tid >> 3;
    int bkr1 = bkr0 + 16;

    float4 av, bv0, bv1;
    av  = *(const float4*)(A + (long)(bm + r) * K + c4);
    bv0 = *(const float4*)(Bm + (long)bkr0 * Dd + bn + c4);
    bv1 = *(const float4*)(Bm + (long)bkr1 * Dd + bn + c4);
    Ast[0][c4+0][r]=av.x; Ast[0][c4+1][r]=av.y; Ast[0][c4+2][r]=av.z; Ast[0][c4+3][r]=av.w;
    *(float4*)&Bst[0][bkr0][c4] = bv0;
    *(float4*)&Bst[0][bkr1][c4] = bv1;
    __syncthreads();

    float a0=0.f, a1=0.f, a2=0.f, a3=0.f;
    const int nit = K / 32;
    int buf = 0;
    for (int it = 0; it < nit; it++) {
        bool more = (it + 1 < nit);
        if (more) {
            int k0n = (it + 1) * 32;
            av  = *(const float4*)(A + (long)(bm + r) * K + k0n + c4);
            bv0 = *(const float4*)(Bm + (long)(k0n + bkr0) * Dd + bn + c4);
            bv1 = *(const float4*)(Bm + (long)(k0n + bkr1) * Dd + bn + c4);
        }
#pragma unroll
        for (int k = 0; k < 32; k++) {
            float a = Ast[buf][k][r];
            float4 b = *(const float4*)&Bst[buf][k][c4];
            a0 = fmaf(a, b.x, a0);
            a1 = fmaf(a, b.y, a1);
            a2 = fmaf(a, b.z, a2);
            a3 = fmaf(a, b.w, a3);
        }
        if (more) {
            int nb = buf ^ 1;
            Ast[nb][c4+0][r]=av.x; Ast[nb][c4+1][r]=av.y;
            Ast[nb][c4+2][r]=av.z; Ast[nb][c4+3][r]=av.w;
            *(float4*)&Bst[nb][bkr0][c4] = bv0;
            *(float4*)&Bst[nb][bkr1][c4] = bv1;
            __syncthreads();
            buf = nb;
        }
    }

    int gm = bm + r, gn = bn + c4;
    C[(long)gm * Dd + gn + 0] = a0;
    C[(long)gm * Dd + gn + 1] = a1;
    C[(long)gm * Dd + gn + 2] = a2;
    C[(long)gm * Dd + gn + 3] = a3;
}

// ------- cross attention v3: stage only u + f_b8 in smem; f_w in registers ----
// smem: u (40KB) + fbs (16KB) + small -> ~57KB, 2-3 blocks/SM.
#define CROSS_SMEM ((Ll*Dd + 8*Dd + 32 + 160 + 160) * (int)sizeof(float))
__global__ void cross_attn8(const float* __restrict__ u,
                            const float* __restrict__ k,
                            const float* __restrict__ bq,
                            const float* __restrict__ f_w,
                            const float* __restrict__ f_b,
                            const float* __restrict__ f_s,
                            float* __restrict__ fbq)
{
    extern __shared__ float sm[];
    float* uw  = sm;                       // [Ll][Dd]
    float* fbs = sm + Ll * Dd;             // [8][Dd]
    float* cv  = fbs + 8 * Dd;             // [Ll] (+pad)
    float* lg  = cv + 32;                  // [160] logits (l*8+n)
    float* wt  = lg + 160;                 // [160] weights

    int b  = blockIdx.y;
    int n0 = blockIdx.x * 8;
    int t  = threadIdx.x;                  // 512
    int w = t >> 5, lane = t & 31;

    // stage u[b] and f_b rows
    const float4* us = (const float4*)(u + (long)b * Ll * Dd);
    for (int i = t; i < (Ll * Dd) / 4; i += 512) ((float4*)uw)[i] = us[i];
    const float4* fbsrc = (const float4*)(f_b + (long)(b * Nn + n0) * Dd);
    for (int i = t; i < (8 * Dd) / 4; i += 512) ((float4*)fbs)[i] = fbsrc[i];

    // f_w column for this thread's d in registers
    float fwreg[Ll];
#pragma unroll
    for (int l = 0; l < Ll; l++) fwreg[l] = f_w[(long)(b * Ll + l) * Dd + t];

    // cv[l] = bq . k[b,l]  (global reads, L2-hit, 4 partials for MLP)
    for (int l = w; l < Ll; l += 16) {
        const float* kr = k + (long)(b * Ll + l) * Dd;
        float p0 = 0.f, p1 = 0.f, p2 = 0.f, p3 = 0.f;
#pragma unroll
        for (int dd = 0; dd < Dd / 32; dd += 4) {
            p0 = fmaf(bq[lane + (dd+0) * 32], kr[lane + (dd+0) * 32], p0);
            p1 = fmaf(bq[lane + (dd+1) * 32], kr[lane + (dd+1) * 32], p1);
            p2 = fmaf(bq[lane + (dd+2) * 32], kr[lane + (dd+2) * 32], p2);
            p3 = fmaf(bq[lane + (dd+3) * 32], kr[lane + (dd+3) * 32], p3);
        }
        float p = (p0 + p1) + (p2 + p3);
#pragma unroll
        for (int off = 16; off > 0; off >>= 1) p += __shfl_xor_sync(0xffffffff, p, off);
        if (lane == 0) cv[l] = p;
    }
    __syncthreads();

    // logits: 160 dots (n,l) from smem
    for (int idx = w; idx < 8 * Ll; idx += 16) {
        int n = idx & 7, l = idx >> 3;
        const float* fr = fbs + n * Dd;
        const float* ur = uw + l * Dd;
        float p = 0.f;
#pragma unroll
        for (int dd = 0; dd < Dd / 32; dd++)
            p = fmaf(fr[lane + dd * 32], ur[lane + dd * 32], p);
#pragma unroll
        for (int off = 16; off > 0; off >>= 1) p += __shfl_xor_sync(0xffffffff, p, off);
        if (lane == 0) lg[l * 8 + n] = (p + cv[l]) * SCALE;
    }
    __syncthreads();

    // per-n softmax over Ll
    if (t < 8) {
        float mx = -1e30f;
#pragma unroll
        for (int l = 0; l < Ll; l++) mx = fmaxf(mx, lg[l * 8 + t]);
        float sum = 0.f;
#pragma unroll
        for (int l = 0; l < Ll; l++) { float e = __expf(lg[l * 8 + t] - mx); wt[l * 8 + t] = e; sum += e; }
        float inv = __fdividef(1.f, sum);
#pragma unroll
        for (int l = 0; l < Ll; l++) wt[l * 8 + t] *= inv;
    }
    __syncthreads();

    // output: per thread d = t, all 8 n; f_w from registers
    float fsv = f_s[(long)b * Dd + t];
#pragma unroll
    for (int n = 0; n < 8; n++) {
        float acc = 0.f;
#pragma unroll
        for (int l = 0; l < Ll; l++) acc = fmaf(wt[l * 8 + n], fwreg[l], acc);
        float v = fbs[n * Dd + t] * (acc + fsv);
        fbq[(long)(b * Nn + n0 + n) * Dd + t] = v;
    }
}

// -------- S split-K GEMM v2: 64 threads, 4x4 register tile, single-sync ----
// grid (4, 4, Bb*KS = 32) -> 512 blocks.
__global__ void s_gemm_kernel(const float* __restrict__ fbq, float* __restrict__ Sp)
{
    int b = blockIdx.z / KS;
    int s = blockIdx.z % KS;
    const float* A = fbq + (long)b * Nn * Dd;
    int bm = blockIdx.y * 32;
    int bn = blockIdx.x * 32;
    int kbase = s * KCH;

    __shared__ float As[KCH][36];   // [k][m], stride 36 -> float4 aligned
    __shared__ float Bs[KCH][36];

    int tid = threadIdx.x;          // 64
    int r    = tid >> 1;            // 0..31
    int half = (tid & 1) * 32;      // 0 or 32

#pragma unroll
    for (int q = 0; q < 8; q++) {
        int col = half + q * 4;     // k-column
        float4 av = *(const float4*)(A + (long)(bm + r) * Dd + kbase + col);
        As[col+0][r]=av.x; As[col+1][r]=av.y; As[col+2][r]=av.z; As[col+3][r]=av.w;
        float4 bv = *(const float4*)(A + (long)(bn + r) * Dd + kbase + col);
        Bs[col+0][r]=bv.x; Bs[col+1][r]=bv.y; Bs[col+2][r]=bv.z; Bs[col+3][r]=bv.w;
    }
    __syncthreads();

    int tr = tid >> 3;              // 0..7 -> m rows tr*4..+3
    int tc = tid & 7;               // 0..7 -> n cols tc*4..+3
    float acc[4][4];
#pragma unroll
    for (int i = 0; i < 4; i++)
#pragma unroll
        for (int j = 0; j < 4; j++) acc[i][j] = 0.f;

#pragma unroll 4
    for (int k = 0; k < KCH; k++) {
        float4 a = *(const float4*)&As[k][tr * 4];
        float4 bb = *(const float4*)&Bs[k][tc * 4];
        acc[0][0] = fmaf(a.x, bb.x, acc[0][0]);
        acc[0][1] = fmaf(a.x, bb.y, acc[0][1]);
        acc[0][2] = fmaf(a.x, bb.z, acc[0][2]);
        acc[0][3] = fmaf(a.x, bb.w, acc[0][3]);
        acc[1][0] = fmaf(a.y, bb.x, acc[1][0]);
        acc[1][1] = fmaf(a.y, bb.y, acc[1][1]);
        acc[1][2] = fmaf(a.y, bb.z, acc[1][2]);
        acc[1][3] = fmaf(a.y, bb.w, acc[1][3]);
        acc[2][0] = fmaf(a.z, bb.x, acc[2][0]);
        acc[2][1] = fmaf(a.z, bb.y, acc[2][1]);
        acc[2][2] = fmaf(a.z, bb.z, acc[2][2]);
        acc[2][3] = fmaf(a.z, bb.w, acc[2][3]);
        acc[3][0] = fmaf(a.w, bb.x, acc[3][0]);
        acc[3][1] = fmaf(a.w, bb.y, acc[3][1]);
        acc[3][2] = fmaf(a.w, bb.z, acc[3][2]);
        acc[3][3] = fmaf(a.w, bb.w, acc[3][3]);
    }

    float* o = Sp + ((long)(s * Bb + b) * Nn) * Nn;
    int gm = bm + tr * 4, gn = bn + tc * 4;
#pragma unroll
    for (int i = 0; i < 4; i++)
        *(float4*)(o + (long)(gm + i) * Nn + gn) =
            make_float4(acc[i][0], acc[i][1], acc[i][2], acc[i][3]);
}

// -------- fused: reduce split-K + row softmax + fbb GEMM ----------------
__global__ void softmax_fbb_kernel(const float* __restrict__ Sp, const float* __restrict__ f_b,
                                   float* __restrict__ S, float* __restrict__ out)
{
    int b  = blockIdx.z;
    int rt = blockIdx.y * 32;
    int dt = blockIdx.x * 64;

    __shared__ float As[Nn][34];
    __shared__ float Bst[32][68];

    int tid = threadIdx.x;

    // phase 1: reduce split-K partials (scaled logits)
    {
        int r  = tid >> 3;
        int c0 = (tid & 7) * 16;
#pragma unroll
        for (int cc = 0; cc < 16; cc += 4) {
            float4 acc4 = make_float4(0.f, 0.f, 0.f, 0.f);
#pragma unroll
            for (int s = 0; s < KS; s++) {
                float4 v = *(const float4*)(Sp + ((long)(s * Bb + b) * Nn + rt + r) * Nn + c0 + cc);
                acc4.x += v.x; acc4.y += v.y; acc4.z += v.z; acc4.w += v.w;
            }
            As[c0+cc+0][r] = acc4.x * SCALE;
            As[c0+cc+1][r] = acc4.y * SCALE;
            As[c0+cc+2][r] = acc4.z * SCALE;
            As[c0+cc+3][r] = acc4.w * SCALE;
        }
    }
    __syncthreads();

    // phase 2: row softmax
    {
        int w = tid >> 5, lane = tid & 31;
#pragma unroll
        for (int rr = w * 4; rr < w * 4 + 4; rr++) {
            float v[4];
#pragma unroll
            for (int j = 0; j < 4; j++) v[j] = As[lane + 32 * j][rr];
            float mx = fmaxf(fmaxf(v[0], v[1]), fmaxf(v[2], v[3]));
#pragma unroll
            for (int off = 16; off > 0; off >>= 1) mx = fmaxf(mx, __shfl_xor_sync(0xffffffff, mx, off));
            float sum = 0.f;
#pragma unroll
            for (int j = 0; j < 4; j++) { v[j] = __expf(v[j] - mx); sum += v[j]; }
#pragma unroll
            for (int off = 16; off > 0; off >>= 1) sum += __shfl_xor_sync(0xffffffff, sum, off);
            float inv = __fdividef(1.f, sum);
#pragma unroll
            for (int j = 0; j < 4; j++) {
                float a = v[j] * inv;
                As[lane + 32 * j][rr] = a;
                if (blockIdx.x == 0) S[((long)(b * Nn) + rt + rr) * Nn + lane + 32 * j] = a;
            }
        }
    }
    __syncthreads();

    // phase 3: out = A_b @ f_b + f_b for this tile
    const float* Bf = f_b + (long)b * Nn * Dd;
    int tr = tid >> 4, tc = tid & 15;
    int bkr0 = tid >> 4, bkr1 = bkr0 + 16;
    int bcol = (tid & 15) * 4;

    float acc[2][4];
#pragma unroll
    for (int i = 0; i < 2; i++)
#pragma unroll
        for (int j = 0; j < 4; j++) acc[i][j] = 0.f;

    for (int m0 = 0; m0 < Nn; m0 += 32) {
        *(float4*)&Bst[bkr0][bcol] = *(const float4*)(Bf + (long)(m0 + bkr0) * Dd + dt + bcol);
        *(float4*)&Bst[bkr1][bcol] = *(const float4*)(Bf + (long)(m0 + bkr1) * Dd + dt + bcol);
        __syncthreads();
#pragma unroll
        for (int k = 0; k < 32; k++) {
            float2 a = *(const float2*)&As[m0 + k][tr * 2];
            float4 bb = *(const float4*)&Bst[k][tc * 4];
            acc[0][0] = fmaf(a.x, bb.x, acc[0][0]);
            acc[0][1] = fmaf(a.x, bb.y, acc[0][1]);
            acc[0][2] = fmaf(a.x, bb.z, acc[0][2]);
            acc[0][3] = fmaf(a.x, bb.w, acc[0][3]);
            acc[1][0] = fmaf(a.y, bb.x, acc[1][0]);
            acc[1][1] = fmaf(a.y, bb.y, acc[1][1]);
            acc[1][2] = fmaf(a.y, bb.z, acc[1][2]);
            acc[1][3] = fmaf(a.y, bb.w, acc[1][3]);
        }
        __syncthreads();
    }

#pragma unroll
    for (int i = 0; i < 2; i++) {
        int gn = rt + tr * 2 + i;
#pragma unroll
        for (int j = 0; j < 4; j++) {
            int gd = dt + tc * 4 + j;
            out[((long)b * Nn + gn) * Dd + gd] = acc[i][j] + Bf[(long)gn * Dd + gd];
        }
    }
}

// -------- gated moment reduction: out += sum_i A[i,j]*fm*sigmoid(fm*s) ----
__global__ void moment_kernel(const float* __restrict__ S,
                              const float* __restrict__ f_m,
                              const float* __restrict__ f_s,
                              float* __restrict__ out)
{
    int j = blockIdx.x, b = blockIdx.y;
    int t = threadIdx.x;                  // 0..511
    int dt = t & 127;                     // d-group: d = 4*dt
    int ig = t >> 7;                      // 0..3

    __shared__ float Acol[Nn];
    __shared__ float4 red[4][128];
    if (t < Nn) Acol[t] = S[(long)(b * Nn + t) * Nn + j];
    __syncthreads();

    float4 s = *(const float4*)(f_s + (long)b * Dd + 4 * dt);
    float hx = 0.5f * s.x, hy = 0.5f * s.y, hz = 0.5f * s.z, hw = 0.5f * s.w;
    const float4* fm = (const float4*)(f_m + ((long)(b * Nn) * Nn + j) * Dd) + dt;
    const long istep = (long)Nn * Dd / 4;

    float ax = 0.f, ay = 0.f, az = 0.f, aw = 0.f;
#pragma unroll 8
    for (int ii = 0; ii < Nn / 4; ii++) {
        int i = ig * (Nn / 4) + ii;
        float4 x = __ldcs(&fm[(long)i * istep]);
        float a = Acol[i];
        ax = fmaf(a * x.x, fmaf(tanh_approx(x.x * hx), 0.5f, 0.5f), ax);
        ay = fmaf(a * x.y, fmaf(tanh_approx(x.y * hy), 0.5f, 0.5f), ay);
        az = fmaf(a * x.z, fmaf(tanh_approx(x.z * hz), 0.5f, 0.5f), az);
        aw = fmaf(a * x.w, fmaf(tanh_approx(x.w * hw), 0.5f, 0.5f), aw);
    }
    red[ig][dt] = make_float4(ax, ay, az, aw);
    __syncthreads();

    if (t < 128) {
        float4 r0 = red[0][t], r1 = red[1][t], r2 = red[2][t], r3 = red[3][t];
        float4* op = (float4*)(out + (long)(b * Nn + j) * Dd) + t;
        float4 r = *op;
        r.x += r0.x + r1.x + r2.x + r3.x;
        r.y += r0.y + r1.y + r2.y + r3.y;
        r.z += r0.z + r1.z + r2.z + r3.z;
        r.w += r0.w + r1.w + r2.w + r3.w;
        *op = r;
    }
}

// ---------------- launch ----------------
extern "C" void kernel_launch(void* const* d_in, const int* in_sizes, int n_in,
                              void* d_out, int out_size)
{
    const float* f_b = (const float*)d_in[0];
    const float* f_w = (const float*)d_in[1];
    const float* f_s = (const float*)d_in[2];
    const float* f_m = (const float*)d_in[3];
    const float* Wq  = (const float*)d_in[4];
    const float* bq  = (const float*)d_in[5];
    const float* Wk  = (const float*)d_in[6];
    const float* bk  = (const float*)d_in[7];
    float* out = (float*)d_out;

    float* kk  = nullptr; cudaGetSymbolAddress((void**)&kk,  g_k);
    float* u   = nullptr; cudaGetSymbolAddress((void**)&u,   g_u);
    float* fbq = nullptr; cudaGetSymbolAddress((void**)&fbq, g_fbq);
    float* S   = nullptr; cudaGetSymbolAddress((void**)&S,   g_S);
    float* Sp  = nullptr; cudaGetSymbolAddress((void**)&Sp,  g_Sp);

    cudaFuncSetAttribute(cross_attn8, cudaFuncAttributeMaxDynamicSharedMemorySize, CROSS_SMEM);

    // 1) k = f_w @ Wk^T + bk   [80,512]
    {
        dim3 grid(Dd / 32, (Bb * Ll) / 16);
        gemm_nt32<<<grid, 128>>>(f_w, Wk, bk, kk);
    }
    // 2) u = k @ Wq            [80,512]
    {
        dim3 grid(Dd / 32, (Bb * Ll) / 16);
        gemm_nn32<<<grid, 128>>>(kk, Wq, u);
    }
    // 3) cross attention + gate -> f_bq
    {
        dim3 grid(Nn / 8, Bb);
        cross_attn8<<<grid, 512, CROSS_SMEM>>>(u, kk, bq, f_w, f_b, f_s, fbq);
    }
    // 4) S partials = split-K f_bq @ f_bq^T
    {
        dim3 grid(Nn / 32, Nn / 32, Bb * KS);
        s_gemm_kernel<<<grid, 64>>>(fbq, Sp);
    }
    // 5) fused reduce + softmax + fbb: writes S and out = A_b@f_b + f_b
    {
        dim3 grid(Dd / 64, Nn / 32, Bb);
        softmax_fbb_kernel<<<grid, 256>>>(Sp, f_b, S, out);
    }
    // 6) moment: out += gated moment reduction
    {
        dim3 grid(Nn, Bb);
        moment_kernel<<<grid, 512>>>(S, f_m, f_s, out);
    }
    (void)in_sizes; (void)n_in; (void)out_size;
}

// round 10
// speedup vs baseline: 1.3664x; 1.3664x over previous
#include <cuda_runtime.h>
#include <math.h>

#define Bb 4
#define Nn 128
#define Ll 20
#define Dd 512
#define SCALE 0.044194173824159216f  // 1/sqrt(512)
#define KS 8                          // split-K factor for S GEMM
#define KCH (Dd / KS)                 // 64

// ---------------- scratch (no allocations allowed) ----------------
__device__ float g_k  [Bb*Ll*Dd];        // k = f_w Wk^T + bk        [80,512]
__device__ float g_u  [Bb*Ll*Dd];        // u = k Wq                 [80,512]
__device__ float g_fbq[Bb*Nn*Dd];        // gated boundary feats     [512,512]
__device__ float g_S  [Bb*Nn*Nn];        // A_b after softmax        [4,128,128]
__device__ float g_Sp [KS*Bb*Nn*Nn];     // split-K partials of S

__device__ __forceinline__ float tanh_approx(float x) {
    float y; asm("tanh.approx.f32 %0, %1;" : "=f"(y) : "f"(x)); return y;
}

// ======== NT GEMM, BM=16 BN=32, 128 threads, double-buffered ========
__global__ void gemm_nt32(const float* __restrict__ A, const float* __restrict__ Bm,
                          const float* __restrict__ bias, float* __restrict__ C)
{
    const int K = Dd;
    int bm = blockIdx.y * 16;
    int bn = blockIdx.x * 32;

    __shared__ float Ast[2][32][18];
    __shared__ float Bst[2][32][36];

    int tid = threadIdx.x;
    int r  = tid >> 3;
    int c4 = (tid & 7) * 4;
    int brow0 = tid >> 3;
    int brow1 = brow0 + 16;

    float4 av, bv0, bv1;
    av  = *(const float4*)(A  + (long)(bm + r) * K + c4);
    bv0 = *(const float4*)(Bm + (long)(bn + brow0) * K + c4);
    bv1 = *(const float4*)(Bm + (long)(bn + brow1) * K + c4);
    Ast[0][c4+0][r]=av.x; Ast[0][c4+1][r]=av.y; Ast[0][c4+2][r]=av.z; Ast[0][c4+3][r]=av.w;
    Bst[0][c4+0][brow0]=bv0.x; Bst[0][c4+1][brow0]=bv0.y;
    Bst[0][c4+2][brow0]=bv0.z; Bst[0][c4+3][brow0]=bv0.w;
    Bst[0][c4+0][brow1]=bv1.x; Bst[0][c4+1][brow1]=bv1.y;
    Bst[0][c4+2][brow1]=bv1.z; Bst[0][c4+3][brow1]=bv1.w;
    __syncthreads();

    float a0=0.f, a1=0.f, a2=0.f, a3=0.f;
    const int nit = K / 32;
    int buf = 0;
    for (int it = 0; it < nit; it++) {
        bool more = (it + 1 < nit);
        if (more) {
            int k0n = (it + 1) * 32;
            av  = *(const float4*)(A  + (long)(bm + r) * K + k0n + c4);
            bv0 = *(const float4*)(Bm + (long)(bn + brow0) * K + k0n + c4);
            bv1 = *(const float4*)(Bm + (long)(bn + brow1) * K + k0n + c4);
        }
#pragma unroll
        for (int k = 0; k < 32; k++) {
            float a = Ast[buf][k][r];
            float4 b = *(const float4*)&Bst[buf][k][c4];
            a0 = fmaf(a, b.x, a0);
            a1 = fmaf(a, b.y, a1);
            a2 = fmaf(a, b.z, a2);
            a3 = fmaf(a, b.w, a3);
        }
        if (more) {
            int nb = buf ^ 1;
            Ast[nb][c4+0][r]=av.x; Ast[nb][c4+1][r]=av.y;
            Ast[nb][c4+2][r]=av.z; Ast[nb][c4+3][r]=av.w;
            Bst[nb][c4+0][brow0]=bv0.x; Bst[nb][c4+1][brow0]=bv0.y;
            Bst[nb][c4+2][brow0]=bv0.z; Bst[nb][c4+3][brow0]=bv0.w;
            Bst[nb][c4+0][brow1]=bv1.x; Bst[nb][c4+1][brow1]=bv1.y;
            Bst[nb][c4+2][brow1]=bv1.z; Bst[nb][c4+3][brow1]=bv1.w;
            __syncthreads();
            buf = nb;
        }
    }

    int gm = bm + r, gn = bn + c4;
    float4 bb = bias ? *(const float4*)(bias + gn) : make_float4(0.f,0.f,0.f,0.f);
    C[(long)gm * Dd + gn + 0] = a0 + bb.x;
    C[(long)gm * Dd + gn + 1] = a1 + bb.y;
    C[(long)gm * Dd + gn + 2] = a2 + bb.z;
    C[(long)gm * Dd + gn + 3] = a3 + bb.w;
}

// ======== NN GEMM, BM=16 BN=32, 128 threads, double-buffered ========
__global__ void gemm_nn32(const float* __restrict__ A, const float* __restrict__ Bm,
                          float* __restrict__ C)
{
    const int K = Dd;
    int bm = blockIdx.y * 16;
    int bn = blockIdx.x * 32;

    __shared__ float Ast[2][32][18];
    __shared__ float Bst[2][32][36];

    int tid = threadIdx.x;
    int r  = tid >> 3;
    int c4 = (tid & 7) * 4;
    int bkr0 = tid >> 3;
    int bkr1 = bkr0 + 16;

    float4 av, bv0, bv1;
    av  = *(const float4*)(A + (long)(bm + r) * K + c4);
    bv0 = *(const float4*)(Bm + (long)bkr0 * Dd + bn + c4);
    bv1 = *(const float4*)(Bm + (long)bkr1 * Dd + bn + c4);
    Ast[0][c4+0][r]=av.x; Ast[0][c4+1][r]=av.y; Ast[0][c4+2][r]=av.z; Ast[0][c4+3][r]=av.w;
    *(float4*)&Bst[0][bkr0][c4] = bv0;
    *(float4*)&Bst[0][bkr1][c4] = bv1;
    __syncthreads();

    float a0=0.f, a1=0.f, a2=0.f, a3=0.f;
    const int nit = K / 32;
    int buf = 0;
    for (int it = 0; it < nit; it++) {
        bool more = (it + 1 < nit);
        if (more) {
            int k0n = (it + 1) * 32;
            av  = *(const float4*)(A + (long)(bm + r) * K + k0n + c4);
            bv0 = *(const float4*)(Bm + (long)(k0n + bkr0) * Dd + bn + c4);
            bv1 = *(const float4*)(Bm + (long)(k0n + bkr1) * Dd + bn + c4);
        }
#pragma unroll
        for (int k = 0; k < 32; k++) {
            float a = Ast[buf][k][r];
            float4 b = *(const float4*)&Bst[buf][k][c4];
            a0 = fmaf(a, b.x, a0);
            a1 = fmaf(a, b.y, a1);
            a2 = fmaf(a, b.z, a2);
            a3 = fmaf(a, b.w, a3);
        }
        if (more) {
            int nb = buf ^ 1;
            Ast[nb][c4+0][r]=av.x; Ast[nb][c4+1][r]=av.y;
            Ast[nb][c4+2][r]=av.z; Ast[nb][c4+3][r]=av.w;
            *(float4*)&Bst[nb][bkr0][c4] = bv0;
            *(float4*)&Bst[nb][bkr1][c4] = bv1;
            __syncthreads();
            buf = nb;
        }
    }

    int gm = bm + r, gn = bn + c4;
    C[(long)gm * Dd + gn + 0] = a0;
    C[(long)gm * Dd + gn + 1] = a1;
    C[(long)gm * Dd + gn + 2] = a2;
    C[(long)gm * Dd + gn + 3] = a3;
}

// ------- cross attention (R8-proven v2): 8 rows per block, all tiles in smem ----
#define CROSS_SMEM ((2*Ll*Dd + 8*Dd + 32 + 160 + 160) * (int)sizeof(float))
__global__ void cross_attn8(const float* __restrict__ u,
                            const float* __restrict__ k,
                            const float* __restrict__ bq,
                            const float* __restrict__ f_w,
                            const float* __restrict__ f_b,
                            const float* __restrict__ f_s,
                            float* __restrict__ fbq)
{
    extern __shared__ float sm[];
    float* uw  = sm;                       // [Ll][Dd]
    float* fw  = sm + Ll * Dd;             // [Ll][Dd]
    float* fbs = fw + Ll * Dd;             // [8][Dd]
    float* cv  = fbs + 8 * Dd;             // [Ll] (+pad)
    float* lg  = cv + 32;                  // [160]
    float* wt  = lg + 160;                 // [160]

    int b  = blockIdx.y;
    int n0 = blockIdx.x * 8;
    int t  = threadIdx.x;                  // 512
    int w = t >> 5, lane = t & 31;

    const float4* us  = (const float4*)(u   + (long)b * Ll * Dd);
    const float4* fws = (const float4*)(f_w + (long)b * Ll * Dd);
    for (int i = t; i < (Ll * Dd) / 4; i += 512) {
        ((float4*)uw)[i] = us[i];
        ((float4*)fw)[i] = fws[i];
    }
    const float4* fbsrc = (const float4*)(f_b + (long)(b * Nn + n0) * Dd);
    for (int i = t; i < (8 * Dd) / 4; i += 512) ((float4*)fbs)[i] = fbsrc[i];

    for (int l = w; l < Ll; l += 16) {
        const float* kr = k + (long)(b * Ll + l) * Dd;
        float p = 0.f;
#pragma unroll
        for (int dd = 0; dd < Dd / 32; dd++)
            p = fmaf(bq[lane + dd * 32], kr[lane + dd * 32], p);
#pragma unroll
        for (int off = 16; off > 0; off >>= 1) p += __shfl_xor_sync(0xffffffff, p, off);
        if (lane == 0) cv[l] = p;
    }
    __syncthreads();

    for (int idx = w; idx < 8 * Ll; idx += 16) {
        int n = idx & 7, l = idx >> 3;
        const float* fr = fbs + n * Dd;
        const float* ur = uw + l * Dd;
        float p = 0.f;
#pragma unroll
        for (int dd = 0; dd < Dd / 32; dd++)
            p = fmaf(fr[lane + dd * 32], ur[lane + dd * 32], p);
#pragma unroll
        for (int off = 16; off > 0; off >>= 1) p += __shfl_xor_sync(0xffffffff, p, off);
        if (lane == 0) lg[l * 8 + n] = (p + cv[l]) * SCALE;
    }
    __syncthreads();

    if (t < 8) {
        float mx = -1e30f;
#pragma unroll
        for (int l = 0; l < Ll; l++) mx = fmaxf(mx, lg[l * 8 + t]);
        float sum = 0.f;
#pragma unroll
        for (int l = 0; l < Ll; l++) { float e = __expf(lg[l * 8 + t] - mx); wt[l * 8 + t] = e; sum += e; }
        float inv = __fdividef(1.f, sum);
#pragma unroll
        for (int l = 0; l < Ll; l++) wt[l * 8 + t] *= inv;
    }
    __syncthreads();

    float fsv = f_s[(long)b * Dd + t];
#pragma unroll
    for (int n = 0; n < 8; n++) {
        float acc = 0.f;
#pragma unroll
        for (int l = 0; l < Ll; l++) acc = fmaf(wt[l * 8 + n], fw[l * Dd + t], acc);
        float v = fbs[n * Dd + t] * (acc + fsv);
        fbq[(long)(b * Nn + n0 + n) * Dd + t] = v;
    }
}

// -------- S split-K GEMM v3: 256 threads, 64x64 tile, 4x4/thread, single-sync ----
// grid (Nn/64=2, 2, Bb*KS=32) -> 128 blocks.
__global__ void s_gemm_kernel(const float* __restrict__ fbq, float* __restrict__ Sp)
{
    int b = blockIdx.z / KS;
    int s = blockIdx.z % KS;
    const float* A = fbq + (long)b * Nn * Dd;
    int bm = blockIdx.y * 64;
    int bn = blockIdx.x * 64;
    int kbase = s * KCH;

    __shared__ float As[KCH][68];   // [k][m], stride 68 -> float4 aligned
    __shared__ float Bs[KCH][68];

    int tid = threadIdx.x;          // 256
    int r  = tid >> 2;              // 0..63 (row of A/B tile)
    int c0 = (tid & 3) * 16;        // k-col base: 0,16,32,48

#pragma unroll
    for (int q = 0; q < 4; q++) {
        int col = c0 + q * 4;
        float4 av = *(const float4*)(A + (long)(bm + r) * Dd + kbase + col);
        As[col+0][r]=av.x; As[col+1][r]=av.y; As[col+2][r]=av.z; As[col+3][r]=av.w;
        float4 bv = *(const float4*)(A + (long)(bn + r) * Dd + kbase + col);
        Bs[col+0][r]=bv.x; Bs[col+1][r]=bv.y; Bs[col+2][r]=bv.z; Bs[col+3][r]=bv.w;
    }
    __syncthreads();

    int tr = tid >> 4;              // 0..15 -> m rows tr*4..+3
    int tc = tid & 15;              // 0..15 -> n cols tc*4..+3
    float acc[4][4];
#pragma unroll
    for (int i = 0; i < 4; i++)
#pragma unroll
        for (int j = 0; j < 4; j++) acc[i][j] = 0.f;

#pragma unroll 4
    for (int k = 0; k < KCH; k++) {
        float4 a  = *(const float4*)&As[k][tr * 4];
        float4 bb = *(const float4*)&Bs[k][tc * 4];
        acc[0][0] = fmaf(a.x, bb.x, acc[0][0]);
        acc[0][1] = fmaf(a.x, bb.y, acc[0][1]);
        acc[0][2] = fmaf(a.x, bb.z, acc[0][2]);
        acc[0][3] = fmaf(a.x, bb.w, acc[0][3]);
        acc[1][0] = fmaf(a.y, bb.x, acc[1][0]);
        acc[1][1] = fmaf(a.y, bb.y, acc[1][1]);
        acc[1][2] = fmaf(a.y, bb.z, acc[1][2]);
        acc[1][3] = fmaf(a.y, bb.w, acc[1][3]);
        acc[2][0] = fmaf(a.z, bb.x, acc[2][0]);
        acc[2][1] = fmaf(a.z, bb.y, acc[2][1]);
        acc[2][2] = fmaf(a.z, bb.z, acc[2][2]);
        acc[2][3] = fmaf(a.z, bb.w, acc[2][3]);
        acc[3][0] = fmaf(a.w, bb.x, acc[3][0]);
        acc[3][1] = fmaf(a.w, bb.y, acc[3][1]);
        acc[3][2] = fmaf(a.w, bb.z, acc[3][2]);
        acc[3][3] = fmaf(a.w, bb.w, acc[3][3]);
    }

    float* o = Sp + ((long)(s * Bb + b) * Nn) * Nn;
    int gm = bm + tr * 4, gn = bn + tc * 4;
#pragma unroll
    for (int i = 0; i < 4; i++)
        *(float4*)(o + (long)(gm + i) * Nn + gn) =
            make_float4(acc[i][0], acc[i][1], acc[i][2], acc[i][3]);
}

// -------- fused: reduce split-K + row softmax + fbb GEMM ----------------
__global__ void softmax_fbb_kernel(const float* __restrict__ Sp, const float* __restrict__ f_b,
                                   float* __restrict__ S, float* __restrict__ out)
{
    int b  = blockIdx.z;
    int rt = blockIdx.y * 32;
    int dt = blockIdx.x * 64;

    __shared__ float As[Nn][34];
    __shared__ float Bst[32][68];

    int tid = threadIdx.x;

    // phase 1: reduce split-K partials (scaled logits)
    {
        int r  = tid >> 3;
        int c0 = (tid & 7) * 16;
#pragma unroll
        for (int cc = 0; cc < 16; cc += 4) {
            float4 acc4 = make_float4(0.f, 0.f, 0.f, 0.f);
#pragma unroll
            for (int s = 0; s < KS; s++) {
                float4 v = *(const float4*)(Sp + ((long)(s * Bb + b) * Nn + rt + r) * Nn + c0 + cc);
                acc4.x += v.x; acc4.y += v.y; acc4.z += v.z; acc4.w += v.w;
            }
            As[c0+cc+0][r] = acc4.x * SCALE;
            As[c0+cc+1][r] = acc4.y * SCALE;
            As[c0+cc+2][r] = acc4.z * SCALE;
            As[c0+cc+3][r] = acc4.w * SCALE;
        }
    }
    __syncthreads();

    // phase 2: row softmax
    {
        int w = tid >> 5, lane = tid & 31;
#pragma unroll
        for (int rr = w * 4; rr < w * 4 + 4; rr++) {
            float v[4];
#pragma unroll
            for (int j = 0; j < 4; j++) v[j] = As[lane + 32 * j][rr];
            float mx = fmaxf(fmaxf(v[0], v[1]), fmaxf(v[2], v[3]));
#pragma unroll
            for (int off = 16; off > 0; off >>= 1) mx = fmaxf(mx, __shfl_xor_sync(0xffffffff, mx, off));
            float sum = 0.f;
#pragma unroll
            for (int j = 0; j < 4; j++) { v[j] = __expf(v[j] - mx); sum += v[j]; }
#pragma unroll
            for (int off = 16; off > 0; off >>= 1) sum += __shfl_xor_sync(0xffffffff, sum, off);
            float inv = __fdividef(1.f, sum);
#pragma unroll
            for (int j = 0; j < 4; j++) {
                float a = v[j] * inv;
                As[lane + 32 * j][rr] = a;
                if (blockIdx.x == 0) S[((long)(b * Nn) + rt + rr) * Nn + lane + 32 * j] = a;
            }
        }
    }
    __syncthreads();

    // phase 3: out = A_b @ f_b + f_b for this tile
    const float* Bf = f_b + (long)b * Nn * Dd;
    int tr = tid >> 4, tc = tid & 15;
    int bkr0 = tid >> 4, bkr1 = bkr0 + 16;
    int bcol = (tid & 15) * 4;

    float acc[2][4];
#pragma unroll
    for (int i = 0; i < 2; i++)
#pragma unroll
        for (int j = 0; j < 4; j++) acc[i][j] = 0.f;

    for (int m0 = 0; m0 < Nn; m0 += 32) {
        *(float4*)&Bst[bkr0][bcol] = *(const float4*)(Bf + (long)(m0 + bkr0) * Dd + dt + bcol);
        *(float4*)&Bst[bkr1][bcol] = *(const float4*)(Bf + (long)(m0 + bkr1) * Dd + dt + bcol);
        __syncthreads();
#pragma unroll
        for (int k = 0; k < 32; k++) {
            float2 a = *(const float2*)&As[m0 + k][tr * 2];
            float4 bb = *(const float4*)&Bst[k][tc * 4];
            acc[0][0] = fmaf(a.x, bb.x, acc[0][0]);
            acc[0][1] = fmaf(a.x, bb.y, acc[0][1]);
            acc[0][2] = fmaf(a.x, bb.z, acc[0][2]);
            acc[0][3] = fmaf(a.x, bb.w, acc[0][3]);
            acc[1][0] = fmaf(a.y, bb.x, acc[1][0]);
            acc[1][1] = fmaf(a.y, bb.y, acc[1][1]);
            acc[1][2] = fmaf(a.y, bb.z, acc[1][2]);
            acc[1][3] = fmaf(a.y, bb.w, acc[1][3]);
        }
        __syncthreads();
    }

#pragma unroll
    for (int i = 0; i < 2; i++) {
        int gn = rt + tr * 2 + i;
#pragma unroll
        for (int j = 0; j < 4; j++) {
            int gd = dt + tc * 4 + j;
            out[((long)b * Nn + gn) * Dd + gd] = acc[i][j] + Bf[(long)gn * Dd + gd];
        }
    }
}

// -------- gated moment reduction: out += sum_i A[i,j]*fm*sigmoid(fm*s) ----
__global__ void moment_kernel(const float* __restrict__ S,
                              const float* __restrict__ f_m,
                              const float* __restrict__ f_s,
                              float* __restrict__ out)
{
    int j = blockIdx.x, b = blockIdx.y;
    int t = threadIdx.x;                  // 0..511
    int dt = t & 127;                     // d-group: d = 4*dt
    int ig = t >> 7;                      // 0..3

    __shared__ float Acol[Nn];
    __shared__ float4 red[4][128];
    if (t < Nn) Acol[t] = S[(long)(b * Nn + t) * Nn + j];
    __syncthreads();

    float4 s = *(const float4*)(f_s + (long)b * Dd + 4 * dt);
    float hx = 0.5f * s.x, hy = 0.5f * s.y, hz = 0.5f * s.z, hw = 0.5f * s.w;
    const float4* fm = (const float4*)(f_m + ((long)(b * Nn) * Nn + j) * Dd) + dt;
    const long istep = (long)Nn * Dd / 4;

    float ax = 0.f, ay = 0.f, az = 0.f, aw = 0.f;
#pragma unroll 8
    for (int ii = 0; ii < Nn / 4; ii++) {
        int i = ig * (Nn / 4) + ii;
        float4 x = __ldcs(&fm[(long)i * istep]);
        float a = Acol[i];
        ax = fmaf(a * x.x, fmaf(tanh_approx(x.x * hx), 0.5f, 0.5f), ax);
        ay = fmaf(a * x.y, fmaf(tanh_approx(x.y * hy), 0.5f, 0.5f), ay);
        az = fmaf(a * x.z, fmaf(tanh_approx(x.z * hz), 0.5f, 0.5f), az);
        aw = fmaf(a * x.w, fmaf(tanh_approx(x.w * hw), 0.5f, 0.5f), aw);
    }
    red[ig][dt] = make_float4(ax, ay, az, aw);
    __syncthreads();

    if (t < 128) {
        float4 r0 = red[0][t], r1 = red[1][t], r2 = red[2][t], r3 = red[3][t];
        float4* op = (float4*)(out + (long)(b * Nn + j) * Dd) + t;
        float4 r = *op;
        r.x += r0.x + r1.x + r2.x + r3.x;
        r.y += r0.y + r1.y + r2.y + r3.y;
        r.z += r0.z + r1.z + r2.z + r3.z;
        r.w += r0.w + r1.w + r2.w + r3.w;
        *op = r;
    }
}

// ---------------- launch ----------------
extern "C" void kernel_launch(void* const* d_in, const int* in_sizes, int n_in,
                              void* d_out, int out_size)
{
    const float* f_b = (const float*)d_in[0];
    const float* f_w = (const float*)d_in[1];
    const float* f_s = (const float*)d_in[2];
    const float* f_m = (const float*)d_in[3];
    const float* Wq  = (const float*)d_in[4];
    const float* bq  = (const float*)d_in[5];
    const float* Wk  = (const float*)d_in[6];
    const float* bk  = (const float*)d_in[7];
    float* out = (float*)d_out;

    float* kk  = nullptr; cudaGetSymbolAddress((void**)&kk,  g_k);
    float* u   = nullptr; cudaGetSymbolAddress((void**)&u,   g_u);
    float* fbq = nullptr; cudaGetSymbolAddress((void**)&fbq, g_fbq);
    float* S   = nullptr; cudaGetSymbolAddress((void**)&S,   g_S);
    float* Sp  = nullptr; cudaGetSymbolAddress((void**)&Sp,  g_Sp);

    cudaFuncSetAttribute(cross_attn8, cudaFuncAttributeMaxDynamicSharedMemorySize, CROSS_SMEM);

    // 1) k = f_w @ Wk^T + bk   [80,512]
    {
        dim3 grid(Dd / 32, (Bb * Ll) / 16);
        gemm_nt32<<<grid, 128>>>(f_w, Wk, bk, kk);
    }
    // 2) u = k @ Wq            [80,512]
    {
        dim3 grid(Dd / 32, (Bb * Ll) / 16);
        gemm_nn32<<<grid, 128>>>(kk, Wq, u);
    }
    // 3) cross attention + gate -> f_bq
    {
        dim3 grid(Nn / 8, Bb);
        cross_attn8<<<grid, 512, CROSS_SMEM>>>(u, kk, bq, f_w, f_b, f_s, fbq);
    }
    // 4) S partials = split-K f_bq @ f_bq^T (64x64 tiles, 4x4/thread)
    {
        dim3 grid(Nn / 64, Nn / 64, Bb * KS);
        s_gemm_kernel<<<grid, 256>>>(fbq, Sp);
    }
    // 5) fused reduce + softmax + fbb: writes S and out = A_b@f_b + f_b
    {
        dim3 grid(Dd / 64, Nn / 32, Bb);
        softmax_fbb_kernel<<<grid, 256>>>(Sp, f_b, S, out);
    }
    // 6) moment: out += gated moment reduction
    {
        dim3 grid(Nn, Bb);
        moment_kernel<<<grid, 512>>>(S, f_m, f_s, out);
    }
    (void)in_sizes; (void)n_in; (void)out_size;
}

// round 11
// speedup vs baseline: 1.4008x; 1.0252x over previous
#include <cuda_runtime.h>
#include <math.h>

#define Bb 4
#define Nn 128
#define Ll 20
#define Dd 512
#define SCALE 0.044194173824159216f  // 1/sqrt(512)
#define KS 16                         // split-K factor for S GEMM
#define KCH (Dd / KS)                 // 32
#define FSK 4                         // split-K factor for front GEMMs
#define FCH (Dd / FSK)                // 128

// ---------------- scratch (no allocations allowed) ----------------
__device__ float g_kp [FSK*Bb*Ll*Dd];    // k partials (no bias)    [4][80][512]
__device__ float g_up [FSK*Bb*Ll*Dd];    // u partials              [4][80][512]
__device__ float g_fbq[Bb*Nn*Dd];        // gated boundary feats    [512,512]
__device__ float g_S  [Bb*Nn*Nn];        // A_b after softmax       [4,128,128]
__device__ float g_Sp [KS*Bb*Nn*Nn];     // split-K partials of S

__device__ __forceinline__ float tanh_approx(float x) {
    float y; asm("tanh.approx.f32 %0, %1;" : "=f"(y) : "f"(x)); return y;
}

#define KSTRIDE ((long)Bb*Ll*Dd)

// ======== split-K NT GEMM: kp[s] = f_w @ Wk^T (chunk s), BM=16 BN=32, 128 thr ====
__global__ void gemm_nt_sk(const float* __restrict__ A, const float* __restrict__ Bm,
                           float* __restrict__ Cp)
{
    const int K = Dd;
    int s  = blockIdx.z;
    int kb = s * FCH;
    int bm = blockIdx.y * 16;
    int bn = blockIdx.x * 32;

    __shared__ float Ast[2][32][18];
    __shared__ float Bst[2][32][36];

    int tid = threadIdx.x;
    int r  = tid >> 3;
    int c4 = (tid & 7) * 4;
    int brow0 = tid >> 3;
    int brow1 = brow0 + 16;

    float4 av, bv0, bv1;
    av  = *(const float4*)(A  + (long)(bm + r) * K + kb + c4);
    bv0 = *(const float4*)(Bm + (long)(bn + brow0) * K + kb + c4);
    bv1 = *(const float4*)(Bm + (long)(bn + brow1) * K + kb + c4);
    Ast[0][c4+0][r]=av.x; Ast[0][c4+1][r]=av.y; Ast[0][c4+2][r]=av.z; Ast[0][c4+3][r]=av.w;
    Bst[0][c4+0][brow0]=bv0.x; Bst[0][c4+1][brow0]=bv0.y;
    Bst[0][c4+2][brow0]=bv0.z; Bst[0][c4+3][brow0]=bv0.w;
    Bst[0][c4+0][brow1]=bv1.x; Bst[0][c4+1][brow1]=bv1.y;
    Bst[0][c4+2][brow1]=bv1.z; Bst[0][c4+3][brow1]=bv1.w;
    __syncthreads();

    float a0=0.f, a1=0.f, a2=0.f, a3=0.f;
    const int nit = FCH / 32;     // 4
    int buf = 0;
    for (int it = 0; it < nit; it++) {
        bool more = (it + 1 < nit);
        if (more) {
            int k0n = kb + (it + 1) * 32;
            av  = *(const float4*)(A  + (long)(bm + r) * K + k0n + c4);
            bv0 = *(const float4*)(Bm + (long)(bn + brow0) * K + k0n + c4);
            bv1 = *(const float4*)(Bm + (long)(bn + brow1) * K + k0n + c4);
        }
#pragma unroll
        for (int k = 0; k < 32; k++) {
            float a = Ast[buf][k][r];
            float4 b = *(const float4*)&Bst[buf][k][c4];
            a0 = fmaf(a, b.x, a0);
            a1 = fmaf(a, b.y, a1);
            a2 = fmaf(a, b.z, a2);
            a3 = fmaf(a, b.w, a3);
        }
        if (more) {
            int nb = buf ^ 1;
            Ast[nb][c4+0][r]=av.x; Ast[nb][c4+1][r]=av.y;
            Ast[nb][c4+2][r]=av.z; Ast[nb][c4+3][r]=av.w;
            Bst[nb][c4+0][brow0]=bv0.x; Bst[nb][c4+1][brow0]=bv0.y;
            Bst[nb][c4+2][brow0]=bv0.z; Bst[nb][c4+3][brow0]=bv0.w;
            Bst[nb][c4+0][brow1]=bv1.x; Bst[nb][c4+1][brow1]=bv1.y;
            Bst[nb][c4+2][brow1]=bv1.z; Bst[nb][c4+3][brow1]=bv1.w;
            __syncthreads();
            buf = nb;
        }
    }

    int gm = bm + r, gn = bn + c4;
    float* o = Cp + ((long)s * Bb * Ll + gm) * Dd + gn;
    o[0] = a0; o[1] = a1; o[2] = a2; o[3] = a3;
}

// sum 4 k-partials + bias at (row, col..col+3)
__device__ __forceinline__ float4 ksum4(const float* __restrict__ kp,
                                        const float* __restrict__ bk,
                                        int row, int col)
{
    const float* p = kp + (long)row * Dd + col;
    float4 a = *(const float4*)(p);
    float4 b = *(const float4*)(p + KSTRIDE);
    float4 c = *(const float4*)(p + 2 * KSTRIDE);
    float4 d = *(const float4*)(p + 3 * KSTRIDE);
    float4 e = *(const float4*)(bk + col);
    return make_float4(a.x+b.x+c.x+d.x+e.x, a.y+b.y+c.y+d.y+e.y,
                       a.z+b.z+c.z+d.z+e.z, a.w+b.w+c.w+d.w+e.w);
}

// ======== split-K NN GEMM: up[s] = k @ Wq (chunk s); k summed from partials ====
__global__ void gemm_nn_sk(const float* __restrict__ kp, const float* __restrict__ bk,
                           const float* __restrict__ Bm, float* __restrict__ Cp)
{
    int s  = blockIdx.z;
    int kb = s * FCH;
    int bm = blockIdx.y * 16;
    int bn = blockIdx.x * 32;

    __shared__ float Ast[2][32][18];
    __shared__ float Bst[2][32][36];

    int tid = threadIdx.x;
    int r  = tid >> 3;
    int c4 = (tid & 7) * 4;
    int bkr0 = tid >> 3;
    int bkr1 = bkr0 + 16;

    float4 av, bv0, bv1;
    av  = ksum4(kp, bk, bm + r, kb + c4);
    bv0 = *(const float4*)(Bm + (long)(kb + bkr0) * Dd + bn + c4);
    bv1 = *(const float4*)(Bm + (long)(kb + bkr1) * Dd + bn + c4);
    Ast[0][c4+0][r]=av.x; Ast[0][c4+1][r]=av.y; Ast[0][c4+2][r]=av.z; Ast[0][c4+3][r]=av.w;
    *(float4*)&Bst[0][bkr0][c4] = bv0;
    *(float4*)&Bst[0][bkr1][c4] = bv1;
    __syncthreads();

    float a0=0.f, a1=0.f, a2=0.f, a3=0.f;
    const int nit = FCH / 32;     // 4
    int buf = 0;
    for (int it = 0; it < nit; it++) {
        bool more = (it + 1 < nit);
        if (more) {
            int k0n = kb + (it + 1) * 32;
            av  = ksum4(kp, bk, bm + r, k0n + c4);
            bv0 = *(const float4*)(Bm + (long)(k0n + bkr0) * Dd + bn + c4);
            bv1 = *(const float4*)(Bm + (long)(k0n + bkr1) * Dd + bn + c4);
        }
#pragma unroll
        for (int k = 0; k < 32; k++) {
            float a = Ast[buf][k][r];
            float4 b = *(const float4*)&Bst[buf][k][c4];
            a0 = fmaf(a, b.x, a0);
            a1 = fmaf(a, b.y, a1);
            a2 = fmaf(a, b.z, a2);
            a3 = fmaf(a, b.w, a3);
        }
        if (more) {
            int nb = buf ^ 1;
            Ast[nb][c4+0][r]=av.x; Ast[nb][c4+1][r]=av.y;
            Ast[nb][c4+2][r]=av.z; Ast[nb][c4+3][r]=av.w;
            *(float4*)&Bst[nb][bkr0][c4] = bv0;
            *(float4*)&Bst[nb][bkr1][c4] = bv1;
            __syncthreads();
            buf = nb;
        }
    }

    int gm = bm + r, gn = bn + c4;
    float* o = Cp + ((long)s * Bb * Ll + gm) * Dd + gn;
    o[0] = a0; o[1] = a1; o[2] = a2; o[3] = a3;
}

// ------- cross attention: 8 rows per block; sums u/k partials while staging ----
#define CROSS_SMEM ((2*Ll*Dd + 8*Dd + 32 + 160 + 160) * (int)sizeof(float))
__global__ void cross_attn8(const float* __restrict__ up,
                            const float* __restrict__ kp,
                            const float* __restrict__ bk,
                            const float* __restrict__ bq,
                            const float* __restrict__ f_w,
                            const float* __restrict__ f_b,
                            const float* __restrict__ f_s,
                            float* __restrict__ fbq)
{
    extern __shared__ float sm[];
    float* uw  = sm;                       // [Ll][Dd] (summed u)
    float* fw  = sm + Ll * Dd;             // [Ll][Dd]
    float* fbs = fw + Ll * Dd;             // [8][Dd]
    float* cv  = fbs + 8 * Dd;             // [Ll] (+pad)
    float* lg  = cv + 32;                  // [160]
    float* wt  = lg + 160;                 // [160]

    int b  = blockIdx.y;
    int n0 = blockIdx.x * 8;
    int t  = threadIdx.x;                  // 512
    int w = t >> 5, lane = t & 31;

    // stage u[b] (sum of 4 partials) and f_w[b]
    const float4* us0 = (const float4*)(up + (long)b * Ll * Dd);
    const float4* us1 = (const float4*)(up + KSTRIDE + (long)b * Ll * Dd);
    const float4* us2 = (const float4*)(up + 2 * KSTRIDE + (long)b * Ll * Dd);
    const float4* us3 = (const float4*)(up + 3 * KSTRIDE + (long)b * Ll * Dd);
    const float4* fws = (const float4*)(f_w + (long)b * Ll * Dd);
    for (int i = t; i < (Ll * Dd) / 4; i += 512) {
        float4 a = us0[i], bb = us1[i], c = us2[i], d = us3[i];
        ((float4*)uw)[i] = make_float4(a.x+bb.x+c.x+d.x, a.y+bb.y+c.y+d.y,
                                       a.z+bb.z+c.z+d.z, a.w+bb.w+c.w+d.w);
        ((float4*)fw)[i] = fws[i];
    }
    const float4* fbsrc = (const float4*)(f_b + (long)(b * Nn + n0) * Dd);
    for (int i = t; i < (8 * Dd) / 4; i += 512) ((float4*)fbs)[i] = fbsrc[i];

    // cv[l] = bq . (k[b,l] summed + bk)
    for (int l = w; l < Ll; l += 16) {
        const float* kr = kp + (long)(b * Ll + l) * Dd;
        float p = 0.f;
#pragma unroll
        for (int dd = 0; dd < Dd / 32; dd++) {
            int idx = lane + dd * 32;
            float kv = kr[idx] + kr[KSTRIDE + idx] + kr[2*KSTRIDE + idx]
                     + kr[3*KSTRIDE + idx] + bk[idx];
            p = fmaf(bq[idx], kv, p);
        }
#pragma unroll
        for (int off = 16; off > 0; off >>= 1) p += __shfl_xor_sync(0xffffffff, p, off);
        if (lane == 0) cv[l] = p;
    }
    __syncthreads();

    for (int idx = w; idx < 8 * Ll; idx += 16) {
        int n = idx & 7, l = idx >> 3;
        const float* fr = fbs + n * Dd;
        const float* ur = uw + l * Dd;
        float p = 0.f;
#pragma unroll
        for (int dd = 0; dd < Dd / 32; dd++)
            p = fmaf(fr[lane + dd * 32], ur[lane + dd * 32], p);
#pragma unroll
        for (int off = 16; off > 0; off >>= 1) p += __shfl_xor_sync(0xffffffff, p, off);
        if (lane == 0) lg[l * 8 + n] = (p + cv[l]) * SCALE;
    }
    __syncthreads();

    if (t < 8) {
        float mx = -1e30f;
#pragma unroll
        for (int l = 0; l < Ll; l++) mx = fmaxf(mx, lg[l * 8 + t]);
        float sum = 0.f;
#pragma unroll
        for (int l = 0; l < Ll; l++) { float e = __expf(lg[l * 8 + t] - mx); wt[l * 8 + t] = e; sum += e; }
        float inv = __fdividef(1.f, sum);
#pragma unroll
        for (int l = 0; l < Ll; l++) wt[l * 8 + t] *= inv;
    }
    __syncthreads();

    float fsv = f_s[(long)b * Dd + t];
#pragma unroll
    for (int n = 0; n < 8; n++) {
        float acc = 0.f;
#pragma unroll
        for (int l = 0; l < Ll; l++) acc = fmaf(wt[l * 8 + n], fw[l * Dd + t], acc);
        float v = fbs[n * Dd + t] * (acc + fsv);
        fbq[(long)(b * Nn + n0 + n) * Dd + t] = v;
    }
}

// -------- S split-K GEMM: KS=16, 64x64 tile, 256 thr, 4x4/thread, single-sync ----
// grid (2, 2, Bb*KS=64) -> 256 blocks.
__global__ void s_gemm_kernel(const float* __restrict__ fbq, float* __restrict__ Sp)
{
    int b = blockIdx.z / KS;
    int s = blockIdx.z % KS;
    const float* A = fbq + (long)b * Nn * Dd;
    int bm = blockIdx.y * 64;
    int bn = blockIdx.x * 64;
    int kbase = s * KCH;

    __shared__ float As[KCH][68];   // [k][m]
    __shared__ float Bs[KCH][68];

    int tid = threadIdx.x;          // 256
    int r  = tid >> 2;              // 0..63
    int c0 = (tid & 3) * 8;         // 0,8,16,24

#pragma unroll
    for (int q = 0; q < 2; q++) {
        int col = c0 + q * 4;
        float4 av = *(const float4*)(A + (long)(bm + r) * Dd + kbase + col);
        As[col+0][r]=av.x; As[col+1][r]=av.y; As[col+2][r]=av.z; As[col+3][r]=av.w;
        float4 bv = *(const float4*)(A + (long)(bn + r) * Dd + kbase + col);
        Bs[col+0][r]=bv.x; Bs[col+1][r]=bv.y; Bs[col+2][r]=bv.z; Bs[col+3][r]=bv.w;
    }
    __syncthreads();

    int tr = tid >> 4;
    int tc = tid & 15;
    float acc[4][4];
#pragma unroll
    for (int i = 0; i < 4; i++)
#pragma unroll
        for (int j = 0; j < 4; j++) acc[i][j] = 0.f;

#pragma unroll 4
    for (int k = 0; k < KCH; k++) {
        float4 a  = *(const float4*)&As[k][tr * 4];
        float4 bb = *(const float4*)&Bs[k][tc * 4];
        acc[0][0] = fmaf(a.x, bb.x, acc[0][0]);
        acc[0][1] = fmaf(a.x, bb.y, acc[0][1]);
        acc[0][2] = fmaf(a.x, bb.z, acc[0][2]);
        acc[0][3] = fmaf(a.x, bb.w, acc[0][3]);
        acc[1][0] = fmaf(a.y, bb.x, acc[1][0]);
        acc[1][1] = fmaf(a.y, bb.y, acc[1][1]);
        acc[1][2] = fmaf(a.y, bb.z, acc[1][2]);
        acc[1][3] = fmaf(a.y, bb.w, acc[1][3]);
        acc[2][0] = fmaf(a.z, bb.x, acc[2][0]);
        acc[2][1] = fmaf(a.z, bb.y, acc[2][1]);
        acc[2][2] = fmaf(a.z, bb.z, acc[2][2]);
        acc[2][3] = fmaf(a.z, bb.w, acc[2][3]);
        acc[3][0] = fmaf(a.w, bb.x, acc[3][0]);
        acc[3][1] = fmaf(a.w, bb.y, acc[3][1]);
        acc[3][2] = fmaf(a.w, bb.z, acc[3][2]);
        acc[3][3] = fmaf(a.w, bb.w, acc[3][3]);
    }

    float* o = Sp + ((long)(s * Bb + b) * Nn) * Nn;
    int gm = bm + tr * 4, gn = bn + tc * 4;
#pragma unroll
    for (int i = 0; i < 4; i++)
        *(float4*)(o + (long)(gm + i) * Nn + gn) =
            make_float4(acc[i][0], acc[i][1], acc[i][2], acc[i][3]);
}

// -------- fused: reduce split-K + row softmax + fbb GEMM ----------------
__global__ void softmax_fbb_kernel(const float* __restrict__ Sp, const float* __restrict__ f_b,
                                   float* __restrict__ S, float* __restrict__ out)
{
    int b  = blockIdx.z;
    int rt = blockIdx.y * 32;
    int dt = blockIdx.x * 64;

    __shared__ float As[Nn][34];
    __shared__ float Bst[32][68];

    int tid = threadIdx.x;

    // phase 1: reduce split-K partials (scaled logits)
    {
        int r  = tid >> 3;
        int c0 = (tid & 7) * 16;
#pragma unroll
        for (int cc = 0; cc < 16; cc += 4) {
            float4 acc4 = make_float4(0.f, 0.f, 0.f, 0.f);
#pragma unroll
            for (int s = 0; s < KS; s++) {
                float4 v = *(const float4*)(Sp + ((long)(s * Bb + b) * Nn + rt + r) * Nn + c0 + cc);
                acc4.x += v.x; acc4.y += v.y; acc4.z += v.z; acc4.w += v.w;
            }
            As[c0+cc+0][r] = acc4.x * SCALE;
            As[c0+cc+1][r] = acc4.y * SCALE;
            As[c0+cc+2][r] = acc4.z * SCALE;
            As[c0+cc+3][r] = acc4.w * SCALE;
        }
    }
    __syncthreads();

    // phase 2: row softmax
    {
        int w = tid >> 5, lane = tid & 31;
#pragma unroll
        for (int rr = w * 4; rr < w * 4 + 4; rr++) {
            float v[4];
#pragma unroll
            for (int j = 0; j < 4; j++) v[j] = As[lane + 32 * j][rr];
            float mx = fmaxf(fmaxf(v[0], v[1]), fmaxf(v[2], v[3]));
#pragma unroll
            for (int off = 16; off > 0; off >>= 1) mx = fmaxf(mx, __shfl_xor_sync(0xffffffff, mx, off));
            float sum = 0.f;
#pragma unroll
            for (int j = 0; j < 4; j++) { v[j] = __expf(v[j] - mx); sum += v[j]; }
#pragma unroll
            for (int off = 16; off > 0; off >>= 1) sum += __shfl_xor_sync(0xffffffff, sum, off);
            float inv = __fdividef(1.f, sum);
#pragma unroll
            for (int j = 0; j < 4; j++) {
                float a = v[j] * inv;
                As[lane + 32 * j][rr] = a;
                if (blockIdx.x == 0) S[((long)(b * Nn) + rt + rr) * Nn + lane + 32 * j] = a;
            }
        }
    }
    __syncthreads();

    // phase 3: out = A_b @ f_b + f_b for this tile
    const float* Bf = f_b + (long)b * Nn * Dd;
    int tr = tid >> 4, tc = tid & 15;
    int bkr0 = tid >> 4, bkr1 = bkr0 + 16;
    int bcol = (tid & 15) * 4;

    float acc[2][4];
#pragma unroll
    for (int i = 0; i < 2; i++)
#pragma unroll
        for (int j = 0; j < 4; j++) acc[i][j] = 0.f;

    for (int m0 = 0; m0 < Nn; m0 += 32) {
        *(float4*)&Bst[bkr0][bcol] = *(const float4*)(Bf + (long)(m0 + bkr0) * Dd + dt + bcol);
        *(float4*)&Bst[bkr1][bcol] = *(const float4*)(Bf + (long)(m0 + bkr1) * Dd + dt + bcol);
        __syncthreads();
#pragma unroll
        for (int k = 0; k < 32; k++) {
            float2 a = *(const float2*)&As[m0 + k][tr * 2];
            float4 bb = *(const float4*)&Bst[k][tc * 4];
            acc[0][0] = fmaf(a.x, bb.x, acc[0][0]);
            acc[0][1] = fmaf(a.x, bb.y, acc[0][1]);
            acc[0][2] = fmaf(a.x, bb.z, acc[0][2]);
            acc[0][3] = fmaf(a.x, bb.w, acc[0][3]);
            acc[1][0] = fmaf(a.y, bb.x, acc[1][0]);
            acc[1][1] = fmaf(a.y, bb.y, acc[1][1]);
            acc[1][2] = fmaf(a.y, bb.z, acc[1][2]);
            acc[1][3] = fmaf(a.y, bb.w, acc[1][3]);
        }
        __syncthreads();
    }

#pragma unroll
    for (int i = 0; i < 2; i++) {
        int gn = rt + tr * 2 + i;
#pragma unroll
        for (int j = 0; j < 4; j++) {
            int gd = dt + tc * 4 + j;
            out[((long)b * Nn + gn) * Dd + gd] = acc[i][j] + Bf[(long)gn * Dd + gd];
        }
    }
}

// -------- gated moment reduction: out += sum_i A[i,j]*fm*sigmoid(fm*s) ----
__global__ void moment_kernel(const float* __restrict__ S,
                              const float* __restrict__ f_m,
                              const float* __restrict__ f_s,
                              float* __restrict__ out)
{
    int j = blockIdx.x, b = blockIdx.y;
    int t = threadIdx.x;                  // 0..511
    int dt = t & 127;                     // d-group: d = 4*dt
    int ig = t >> 7;                      // 0..3

    __shared__ float Acol[Nn];
    __shared__ float4 red[4][128];
    if (t < Nn) Acol[t] = S[(long)(b * Nn + t) * Nn + j];
    __syncthreads();

    float4 s = *(const float4*)(f_s + (long)b * Dd + 4 * dt);
    float hx = 0.5f * s.x, hy = 0.5f * s.y, hz = 0.5f * s.z, hw = 0.5f * s.w;
    const float4* fm = (const float4*)(f_m + ((long)(b * Nn) * Nn + j) * Dd) + dt;
    const long istep = (long)Nn * Dd / 4;

    float ax = 0.f, ay = 0.f, az = 0.f, aw = 0.f;
#pragma unroll 8
    for (int ii = 0; ii < Nn / 4; ii++) {
        int i = ig * (Nn / 4) + ii;
        float4 x = __ldcs(&fm[(long)i * istep]);
        float a = Acol[i];
        ax = fmaf(a * x.x, fmaf(tanh_approx(x.x * hx), 0.5f, 0.5f), ax);
        ay = fmaf(a * x.y, fmaf(tanh_approx(x.y * hy), 0.5f, 0.5f), ay);
        az = fmaf(a * x.z, fmaf(tanh_approx(x.z * hz), 0.5f, 0.5f), az);
        aw = fmaf(a * x.w, fmaf(tanh_approx(x.w * hw), 0.5f, 0.5f), aw);
    }
    red[ig][dt] = make_float4(ax, ay, az, aw);
    __syncthreads();

    if (t < 128) {
        float4 r0 = red[0][t], r1 = red[1][t], r2 = red[2][t], r3 = red[3][t];
        float4* op = (float4*)(out + (long)(b * Nn + j) * Dd) + t;
        float4 r = *op;
        r.x += r0.x + r1.x + r2.x + r3.x;
        r.y += r0.y + r1.y + r2.y + r3.y;
        r.z += r0.z + r1.z + r2.z + r3.z;
        r.w += r0.w + r1.w + r2.w + r3.w;
        *op = r;
    }
}

// ---------------- launch ----------------
extern "C" void kernel_launch(void* const* d_in, const int* in_sizes, int n_in,
                              void* d_out, int out_size)
{
    const float* f_b = (const float*)d_in[0];
    const float* f_w = (const float*)d_in[1];
    const float* f_s = (const float*)d_in[2];
    const float* f_m = (const float*)d_in[3];
    const float* Wq  = (const float*)d_in[4];
    const float* bq  = (const float*)d_in[5];
    const float* Wk  = (const float*)d_in[6];
    const float* bk  = (const float*)d_in[7];
    float* out = (float*)d_out;

    float* kp  = nullptr; cudaGetSymbolAddress((void**)&kp,  g_kp);
    float* up  = nullptr; cudaGetSymbolAddress((void**)&up,  g_up);
    float* fbq = nullptr; cudaGetSymbolAddress((void**)&fbq, g_fbq);
    float* S   = nullptr; cudaGetSymbolAddress((void**)&S,   g_S);
    float* Sp  = nullptr; cudaGetSymbolAddress((void**)&Sp,  g_Sp);

    cudaFuncSetAttribute(cross_attn8, cudaFuncAttributeMaxDynamicSharedMemorySize, CROSS_SMEM);

    // 1) kp[s] = f_w @ Wk^T (chunk s)   [4][80,512]
    {
        dim3 grid(Dd / 32, (Bb * Ll) / 16, FSK);
        gemm_nt_sk<<<grid, 128>>>(f_w, Wk, kp);
    }
    // 2) up[s] = (sum kp + bk) @ Wq (chunk s)
    {
        dim3 grid(Dd / 32, (Bb * Ll) / 16, FSK);
        gemm_nn_sk<<<grid, 128>>>(kp, bk, Wq, up);
    }
    // 3) cross attention + gate -> f_bq (sums partials while staging)
    {
        dim3 grid(Nn / 8, Bb);
        cross_attn8<<<grid, 512, CROSS_SMEM>>>(up, kp, bk, bq, f_w, f_b, f_s, fbq);
    }
    // 4) S partials = split-K f_bq @ f_bq^T (KS=16)
    {
        dim3 grid(Nn / 64, Nn / 64, Bb * KS);
        s_gemm_kernel<<<grid, 256>>>(fbq, Sp);
    }
    // 5) fused reduce + softmax + fbb: writes S and out = A_b@f_b + f_b
    {
        dim3 grid(Dd / 64, Nn / 32, Bb);
        softmax_fbb_kernel<<<grid, 256>>>(Sp, f_b, S, out);
    }
    // 6) moment: out += gated moment reduction
    {
        dim3 grid(Nn, Bb);
        moment_kernel<<<grid, 512>>>(S, f_m, f_s, out);
    }
    (void)in_sizes; (void)n_in; (void)out_size;
}

// round 16
// speedup vs baseline: 1.4890x; 1.0629x over previous
#include <cuda_runtime.h>
#include <cuda_fp16.h>
#include <math.h>

#define Bb 4
#define Nn 128
#define Ll 20
#define Dd 512
#define SCALE 0.044194173824159216f  // 1/sqrt(512)
#define KS 16                         // split-K factor for S GEMM
#define KCH (Dd / KS)                 // 32
#define FSK 4                         // split-K factor for front GEMMs
#define FCH (Dd / FSK)                // 128

// ---------------- scratch (no allocations allowed) ----------------
__device__ float g_kp [FSK*Bb*Ll*Dd];    // k partials (no bias)    [4][80][512]
__device__ float g_up [FSK*Bb*Ll*Dd];    // u partials              [4][80][512]
__device__ float g_fbq[Bb*Nn*Dd];        // gated boundary feats    [512,512]
__device__ float g_S  [Bb*Nn*Nn];        // A_b after softmax       [4,128,128]
__device__ float g_Sp [KS*Bb*Nn*Nn];     // split-K partials of S

__device__ __forceinline__ unsigned tanh2_f16(unsigned x) {
    unsigned y; asm("tanh.approx.f16x2 %0, %1;" : "=r"(y) : "r"(x)); return y;
}

#define KSTRIDE ((long)Bb*Ll*Dd)

// ======== split-K NT GEMM: kp[s] = f_w @ Wk^T (chunk s), BM=16 BN=32, 128 thr ====
__global__ void gemm_nt_sk(const float* __restrict__ A, const float* __restrict__ Bm,
                           float* __restrict__ Cp)
{
    const int K = Dd;
    int s  = blockIdx.z;
    int kb = s * FCH;
    int bm = blockIdx.y * 16;
    int bn = blockIdx.x * 32;

    __shared__ float Ast[2][32][18];
    __shared__ float Bst[2][32][36];

    int tid = threadIdx.x;
    int r  = tid >> 3;
    int c4 = (tid & 7) * 4;
    int brow0 = tid >> 3;
    int brow1 = brow0 + 16;

    float4 av, bv0, bv1;
    av  = *(const float4*)(A  + (long)(bm + r) * K + kb + c4);
    bv0 = *(const float4*)(Bm + (long)(bn + brow0) * K + kb + c4);
    bv1 = *(const float4*)(Bm + (long)(bn + brow1) * K + kb + c4);
    Ast[0][c4+0][r]=av.x; Ast[0][c4+1][r]=av.y; Ast[0][c4+2][r]=av.z; Ast[0][c4+3][r]=av.w;
    Bst[0][c4+0][brow0]=bv0.x; Bst[0][c4+1][brow0]=bv0.y;
    Bst[0][c4+2][brow0]=bv0.z; Bst[0][c4+3][brow0]=bv0.w;
    Bst[0][c4+0][brow1]=bv1.x; Bst[0][c4+1][brow1]=bv1.y;
    Bst[0][c4+2][brow1]=bv1.z; Bst[0][c4+3][brow1]=bv1.w;
    __syncthreads();

    float a0=0.f, a1=0.f, a2=0.f, a3=0.f;
    const int nit = FCH / 32;     // 4
    int buf = 0;
    for (int it = 0; it < nit; it++) {
        bool more = (it + 1 < nit);
        if (more) {
            int k0n = kb + (it + 1) * 32;
            av  = *(const float4*)(A  + (long)(bm + r) * K + k0n + c4);
            bv0 = *(const float4*)(Bm + (long)(bn + brow0) * K + k0n + c4);
            bv1 = *(const float4*)(Bm + (long)(bn + brow1) * K + k0n + c4);
        }
#pragma unroll
        for (int k = 0; k < 32; k++) {
            float a = Ast[buf][k][r];
            float4 b = *(const float4*)&Bst[buf][k][c4];
            a0 = fmaf(a, b.x, a0);
            a1 = fmaf(a, b.y, a1);
            a2 = fmaf(a, b.z, a2);
            a3 = fmaf(a, b.w, a3);
        }
        if (more) {
            int nb = buf ^ 1;
            Ast[nb][c4+0][r]=av.x; Ast[nb][c4+1][r]=av.y;
            Ast[nb][c4+2][r]=av.z; Ast[nb][c4+3][r]=av.w;
            Bst[nb][c4+0][brow0]=bv0.x; Bst[nb][c4+1][brow0]=bv0.y;
            Bst[nb][c4+2][brow0]=bv0.z; Bst[nb][c4+3][brow0]=bv0.w;
            Bst[nb][c4+0][brow1]=bv1.x; Bst[nb][c4+1][brow1]=bv1.y;
            Bst[nb][c4+2][brow1]=bv1.z; Bst[nb][c4+3][brow1]=bv1.w;
            __syncthreads();
            buf = nb;
        }
    }

    int gm = bm + r, gn = bn + c4;
    float* o = Cp + ((long)s * Bb * Ll + gm) * Dd + gn;
    o[0] = a0; o[1] = a1; o[2] = a2; o[3] = a3;
}

// sum 4 k-partials + bias at (row, col..col+3)
__device__ __forceinline__ float4 ksum4(const float* __restrict__ kp,
                                        const float* __restrict__ bk,
                                        int row, int col)
{
    const float* p = kp + (long)row * Dd + col;
    float4 a = *(const float4*)(p);
    float4 b = *(const float4*)(p + KSTRIDE);
    float4 c = *(const float4*)(p + 2 * KSTRIDE);
    float4 d = *(const float4*)(p + 3 * KSTRIDE);
    float4 e = *(const float4*)(bk + col);
    return make_float4(a.x+b.x+c.x+d.x+e.x, a.y+b.y+c.y+d.y+e.y,
                       a.z+b.z+c.z+d.z+e.z, a.w+b.w+c.w+d.w+e.w);
}

// ======== split-K NN GEMM: up[s] = k @ Wq (chunk s); k summed from partials ====
__global__ void gemm_nn_sk(const float* __restrict__ kp, const float* __restrict__ bk,
                           const float* __restrict__ Bm, float* __restrict__ Cp)
{
    int s  = blockIdx.z;
    int kb = s * FCH;
    int bm = blockIdx.y * 16;
    int bn = blockIdx.x * 32;

    __shared__ float Ast[2][32][18];
    __shared__ float Bst[2][32][36];

    int tid = threadIdx.x;
    int r  = tid >> 3;
    int c4 = (tid & 7) * 4;
    int bkr0 = tid >> 3;
    int bkr1 = bkr0 + 16;

    float4 av, bv0, bv1;
    av  = ksum4(kp, bk, bm + r, kb + c4);
    bv0 = *(const float4*)(Bm + (long)(kb + bkr0) * Dd + bn + c4);
    bv1 = *(const float4*)(Bm + (long)(kb + bkr1) * Dd + bn + c4);
    Ast[0][c4+0][r]=av.x; Ast[0][c4+1][r]=av.y; Ast[0][c4+2][r]=av.z; Ast[0][c4+3][r]=av.w;
    *(float4*)&Bst[0][bkr0][c4] = bv0;
    *(float4*)&Bst[0][bkr1][c4] = bv1;
    __syncthreads();

    float a0=0.f, a1=0.f, a2=0.f, a3=0.f;
    const int nit = FCH / 32;     // 4
    int buf = 0;
    for (int it = 0; it < nit; it++) {
        bool more = (it + 1 < nit);
        if (more) {
            int k0n = kb + (it + 1) * 32;
            av  = ksum4(kp, bk, bm + r, k0n + c4);
            bv0 = *(const float4*)(Bm + (long)(k0n + bkr0) * Dd + bn + c4);
            bv1 = *(const float4*)(Bm + (long)(k0n + bkr1) * Dd + bn + c4);
        }
#pragma unroll
        for (int k = 0; k < 32; k++) {
            float a = Ast[buf][k][r];
            float4 b = *(const float4*)&Bst[buf][k][c4];
            a0 = fmaf(a, b.x, a0);
            a1 = fmaf(a, b.y, a1);
            a2 = fmaf(a, b.z, a2);
            a3 = fmaf(a, b.w, a3);
        }
        if (more) {
            int nb = buf ^ 1;
            Ast[nb][c4+0][r]=av.x; Ast[nb][c4+1][r]=av.y;
            Ast[nb][c4+2][r]=av.z; Ast[nb][c4+3][r]=av.w;
            *(float4*)&Bst[nb][bkr0][c4] = bv0;
            *(float4*)&Bst[nb][bkr1][c4] = bv1;
            __syncthreads();
            buf = nb;
        }
    }

    int gm = bm + r, gn = bn + c4;
    float* o = Cp + ((long)s * Bb * Ll + gm) * Dd + gn;
    o[0] = a0; o[1] = a1; o[2] = a2; o[3] = a3;
}

// ------- cross attention: 8 rows per block; sums u/k partials while staging ----
#define CROSS_SMEM ((2*Ll*Dd + 8*Dd + 32 + 160 + 160) * (int)sizeof(float))
__global__ void cross_attn8(const float* __restrict__ up,
                            const float* __restrict__ kp,
                            const float* __restrict__ bk,
                            const float* __restrict__ bq,
                            const float* __restrict__ f_w,
                            const float* __restrict__ f_b,
                            const float* __restrict__ f_s,
                            float* __restrict__ fbq)
{
    extern __shared__ float sm[];
    float* uw  = sm;                       // [Ll][Dd] (summed u)
    float* fw  = sm + Ll * Dd;             // [Ll][Dd]
    float* fbs = fw + Ll * Dd;             // [8][Dd]
    float* cv  = fbs + 8 * Dd;             // [Ll] (+pad)
    float* lg  = cv + 32;                  // [160]
    float* wt  = lg + 160;                 // [160]

    int b  = blockIdx.y;
    int n0 = blockIdx.x * 8;
    int t  = threadIdx.x;                  // 512
    int w = t >> 5, lane = t & 31;

    const float4* us0 = (const float4*)(up + (long)b * Ll * Dd);
    const float4* us1 = (const float4*)(up + KSTRIDE + (long)b * Ll * Dd);
    const float4* us2 = (const float4*)(up + 2 * KSTRIDE + (long)b * Ll * Dd);
    const float4* us3 = (const float4*)(up + 3 * KSTRIDE + (long)b * Ll * Dd);
    const float4* fws = (const float4*)(f_w + (long)b * Ll * Dd);
    for (int i = t; i < (Ll * Dd) / 4; i += 512) {
        float4 a = us0[i], bb = us1[i], c = us2[i], d = us3[i];
        ((float4*)uw)[i] = make_float4(a.x+bb.x+c.x+d.x, a.y+bb.y+c.y+d.y,
                                       a.z+bb.z+c.z+d.z, a.w+bb.w+c.w+d.w);
        ((float4*)fw)[i] = fws[i];
    }
    const float4* fbsrc = (const float4*)(f_b + (long)(b * Nn + n0) * Dd);
    for (int i = t; i < (8 * Dd) / 4; i += 512) ((float4*)fbs)[i] = fbsrc[i];

    // cv[l] = bq . (k[b,l] summed + bk)
    for (int l = w; l < Ll; l += 16) {
        const float* kr = kp + (long)(b * Ll + l) * Dd;
        float p = 0.f;
#pragma unroll
        for (int dd = 0; dd < Dd / 32; dd++) {
            int idx = lane + dd * 32;
            float kv = kr[idx] + kr[KSTRIDE + idx] + kr[2*KSTRIDE + idx]
                     + kr[3*KSTRIDE + idx] + bk[idx];
            p = fmaf(bq[idx], kv, p);
        }
#pragma unroll
        for (int off = 16; off > 0; off >>= 1) p += __shfl_xor_sync(0xffffffff, p, off);
        if (lane == 0) cv[l] = p;
    }
    __syncthreads();

    for (int idx = w; idx < 8 * Ll; idx += 16) {
        int n = idx & 7, l = idx >> 3;
        const float* fr = fbs + n * Dd;
        const float* ur = uw + l * Dd;
        float p = 0.f;
#pragma unroll
        for (int dd = 0; dd < Dd / 32; dd++)
            p = fmaf(fr[lane + dd * 32], ur[lane + dd * 32], p);
#pragma unroll
        for (int off = 16; off > 0; off >>= 1) p += __shfl_xor_sync(0xffffffff, p, off);
        if (lane == 0) lg[l * 8 + n] = (p + cv[l]) * SCALE;
    }
    __syncthreads();

    if (t < 8) {
        float mx = -1e30f;
#pragma unroll
        for (int l = 0; l < Ll; l++) mx = fmaxf(mx, lg[l * 8 + t]);
        float sum = 0.f;
#pragma unroll
        for (int l = 0; l < Ll; l++) { float e = __expf(lg[l * 8 + t] - mx); wt[l * 8 + t] = e; sum += e; }
        float inv = __fdividef(1.f, sum);
#pragma unroll
        for (int l = 0; l < Ll; l++) wt[l * 8 + t] *= inv;
    }
    __syncthreads();

    float fsv = f_s[(long)b * Dd + t];
#pragma unroll
    for (int n = 0; n < 8; n++) {
        float acc = 0.f;
#pragma unroll
        for (int l = 0; l < Ll; l++) acc = fmaf(wt[l * 8 + n], fw[l * Dd + t], acc);
        float v = fbs[n * Dd + t] * (acc + fsv);
        fbq[(long)(b * Nn + n0 + n) * Dd + t] = v;
    }
}

// -------- S split-K GEMM: KS=16, 64x64 tile, 256 thr, 4x4/thread, single-sync ----
__global__ void s_gemm_kernel(const float* __restrict__ fbq, float* __restrict__ Sp)
{
    int b = blockIdx.z / KS;
    int s = blockIdx.z % KS;
    const float* A = fbq + (long)b * Nn * Dd;
    int bm = blockIdx.y * 64;
    int bn = blockIdx.x * 64;
    int kbase = s * KCH;

    __shared__ float As[KCH][68];   // [k][m]
    __shared__ float Bs[KCH][68];

    int tid = threadIdx.x;          // 256
    int r  = tid >> 2;              // 0..63
    int c0 = (tid & 3) * 8;         // 0,8,16,24

#pragma unroll
    for (int q = 0; q < 2; q++) {
        int col = c0 + q * 4;
        float4 av = *(const float4*)(A + (long)(bm + r) * Dd + kbase + col);
        As[col+0][r]=av.x; As[col+1][r]=av.y; As[col+2][r]=av.z; As[col+3][r]=av.w;
        float4 bv = *(const float4*)(A + (long)(bn + r) * Dd + kbase + col);
        Bs[col+0][r]=bv.x; Bs[col+1][r]=bv.y; Bs[col+2][r]=bv.z; Bs[col+3][r]=bv.w;
    }
    __syncthreads();

    int tr = tid >> 4;
    int tc = tid & 15;
    float acc[4][4];
#pragma unroll
    for (int i = 0; i < 4; i++)
#pragma unroll
        for (int j = 0; j < 4; j++) acc[i][j] = 0.f;

#pragma unroll 4
    for (int k = 0; k < KCH; k++) {
        float4 a  = *(const float4*)&As[k][tr * 4];
        float4 bb = *(const float4*)&Bs[k][tc * 4];
        acc[0][0] = fmaf(a.x, bb.x, acc[0][0]);
        acc[0][1] = fmaf(a.x, bb.y, acc[0][1]);
        acc[0][2] = fmaf(a.x, bb.z, acc[0][2]);
        acc[0][3] = fmaf(a.x, bb.w, acc[0][3]);
        acc[1][0] = fmaf(a.y, bb.x, acc[1][0]);
        acc[1][1] = fmaf(a.y, bb.y, acc[1][1]);
        acc[1][2] = fmaf(a.y, bb.z, acc[1][2]);
        acc[1][3] = fmaf(a.y, bb.w, acc[1][3]);
        acc[2][0] = fmaf(a.z, bb.x, acc[2][0]);
        acc[2][1] = fmaf(a.z, bb.y, acc[2][1]);
        acc[2][2] = fmaf(a.z, bb.z, acc[2][2]);
        acc[2][3] = fmaf(a.z, bb.w, acc[2][3]);
        acc[3][0] = fmaf(a.w, bb.x, acc[3][0]);
        acc[3][1] = fmaf(a.w, bb.y, acc[3][1]);
        acc[3][2] = fmaf(a.w, bb.z, acc[3][2]);
        acc[3][3] = fmaf(a.w, bb.w, acc[3][3]);
    }

    float* o = Sp + ((long)(s * Bb + b) * Nn) * Nn;
    int gm = bm + tr * 4, gn = bn + tc * 4;
#pragma unroll
    for (int i = 0; i < 4; i++)
        *(float4*)(o + (long)(gm + i) * Nn + gn) =
            make_float4(acc[i][0], acc[i][1], acc[i][2], acc[i][3]);
}

// -------- fused: reduce split-K + row softmax + fbb GEMM ----------------
__global__ void softmax_fbb_kernel(const float* __restrict__ Sp, const float* __restrict__ f_b,
                                   float* __restrict__ S, float* __restrict__ out)
{
    int b  = blockIdx.z;
    int rt = blockIdx.y * 32;
    int dt = blockIdx.x * 64;

    __shared__ float As[Nn][34];
    __shared__ float Bst[32][68];

    int tid = threadIdx.x;

    // phase 1: reduce split-K partials (scaled logits)
    {
        int r  = tid >> 3;
        int c0 = (tid & 7) * 16;
#pragma unroll
        for (int cc = 0; cc < 16; cc += 4) {
            float4 acc4 = make_float4(0.f, 0.f, 0.f, 0.f);
#pragma unroll
            for (int s = 0; s < KS; s++) {
                float4 v = *(const float4*)(Sp + ((long)(s * Bb + b) * Nn + rt + r) * Nn + c0 + cc);
                acc4.x += v.x; acc4.y += v.y; acc4.z += v.z; acc4.w += v.w;
            }
            As[c0+cc+0][r] = acc4.x * SCALE;
            As[c0+cc+1][r] = acc4.y * SCALE;
            As[c0+cc+2][r] = acc4.z * SCALE;
            As[c0+cc+3][r] = acc4.w * SCALE;
        }
    }
    __syncthreads();

    // phase 2: row softmax
    {
        int w = tid >> 5, lane = tid & 31;
#pragma unroll
        for (int rr = w * 4; rr < w * 4 + 4; rr++) {
            float v[4];
#pragma unroll
            for (int j = 0; j < 4; j++) v[j] = As[lane + 32 * j][rr];
            float mx = fmaxf(fmaxf(v[0], v[1]), fmaxf(v[2], v[3]));
#pragma unroll
            for (int off = 16; off > 0; off >>= 1) mx = fmaxf(mx, __shfl_xor_sync(0xffffffff, mx, off));
            float sum = 0.f;
#pragma unroll
            for (int j = 0; j < 4; j++) { v[j] = __expf(v[j] - mx); sum += v[j]; }
#pragma unroll
            for (int off = 16; off > 0; off >>= 1) sum += __shfl_xor_sync(0xffffffff, sum, off);
            float inv = __fdividef(1.f, sum);
#pragma unroll
            for (int j = 0; j < 4; j++) {
                float a = v[j] * inv;
                As[lane + 32 * j][rr] = a;
                if (blockIdx.x == 0) S[((long)(b * Nn) + rt + rr) * Nn + lane + 32 * j] = a;
            }
        }
    }
    __syncthreads();

    // phase 3: out = A_b @ f_b + f_b for this tile
    const float* Bf = f_b + (long)b * Nn * Dd;
    int tr = tid >> 4, tc = tid & 15;
    int bkr0 = tid >> 4, bkr1 = bkr0 + 16;
    int bcol = (tid & 15) * 4;

    float acc[2][4];
#pragma unroll
    for (int i = 0; i < 2; i++)
#pragma unroll
        for (int j = 0; j < 4; j++) acc[i][j] = 0.f;

    for (int m0 = 0; m0 < Nn; m0 += 32) {
        *(float4*)&Bst[bkr0][bcol] = *(const float4*)(Bf + (long)(m0 + bkr0) * Dd + dt + bcol);
        *(float4*)&Bst[bkr1][bcol] = *(const float4*)(Bf + (long)(m0 + bkr1) * Dd + dt + bcol);
        __syncthreads();
#pragma unroll
        for (int k = 0; k < 32; k++) {
            float2 a = *(const float2*)&As[m0 + k][tr * 2];
            float4 bb = *(const float4*)&Bst[k][tc * 4];
            acc[0][0] = fmaf(a.x, bb.x, acc[0][0]);
            acc[0][1] = fmaf(a.x, bb.y, acc[0][1]);
            acc[0][2] = fmaf(a.x, bb.z, acc[0][2]);
            acc[0][3] = fmaf(a.x, bb.w, acc[0][3]);
            acc[1][0] = fmaf(a.y, bb.x, acc[1][0]);
            acc[1][1] = fmaf(a.y, bb.y, acc[1][1]);
            acc[1][2] = fmaf(a.y, bb.z, acc[1][2]);
            acc[1][3] = fmaf(a.y, bb.w, acc[1][3]);
        }
        __syncthreads();
    }

#pragma unroll
    for (int i = 0; i < 2; i++) {
        int gn = rt + tr * 2 + i;
#pragma unroll
        for (int j = 0; j < 4; j++) {
            int gd = dt + tc * 4 + j;
            out[((long)b * Nn + gn) * Dd + gd] = acc[i][j] + Bf[(long)gn * Dd + gd];
        }
    }
}

// -------- gated moment reduction: out += sum_i A[i,j]*fm*sigmoid(fm*s) ----
// f16x2 packed tanh: 2 sigmoids per MUFU issue. Args scaled in fp32,
// accumulation in fp32.
__global__ void moment_kernel(const float* __restrict__ S,
                              const float* __restrict__ f_m,
                              const float* __restrict__ f_s,
                              float* __restrict__ out)
{
    int j = blockIdx.x, b = blockIdx.y;
    int t = threadIdx.x;                  // 0..511
    int dt = t & 127;                     // d-group: d = 4*dt
    int ig = t >> 7;                      // 0..3

    __shared__ float Acol[Nn];
    __shared__ float4 red[4][128];
    if (t < Nn) Acol[t] = S[(long)(b * Nn + t) * Nn + j];
    __syncthreads();

    float4 s = *(const float4*)(f_s + (long)b * Dd + 4 * dt);
    float hx = 0.5f * s.x, hy = 0.5f * s.y, hz = 0.5f * s.z, hw = 0.5f * s.w;
    const float4* fm = (const float4*)(f_m + ((long)(b * Nn) * Nn + j) * Dd) + dt;
    const long istep = (long)Nn * Dd / 4;

    const __half2 h05 = __float2half2_rn(0.5f);
    float ax = 0.f, ay = 0.f, az = 0.f, aw = 0.f;
#pragma unroll 8
    for (int ii = 0; ii < Nn / 4; ii++) {
        int i = ig * (Nn / 4) + ii;
        float4 x = __ldcs(&fm[(long)i * istep]);
        float a = Acol[i];
        // packed half2 tanh: t = tanh(x*s/2); sig = 0.5*t + 0.5
        __half2 p01 = __floats2half2_rn(x.x * hx, x.y * hy);
        __half2 p23 = __floats2half2_rn(x.z * hz, x.w * hw);
        unsigned u01 = tanh2_f16(*(unsigned*)&p01);
        unsigned u23 = tanh2_f16(*(unsigned*)&p23);
        __half2 s01 = __hfma2(*(__half2*)&u01, h05, h05);
        __half2 s23 = __hfma2(*(__half2*)&u23, h05, h05);
        float2 f01 = __half22float2(s01);
        float2 f23 = __half22float2(s23);
        ax = fmaf(a * x.x, f01.x, ax);
        ay = fmaf(a * x.y, f01.y, ay);
        az = fmaf(a * x.z, f23.x, az);
        aw = fmaf(a * x.w, f23.y, aw);
    }
    red[ig][dt] = make_float4(ax, ay, az, aw);
    __syncthreads();

    if (t < 128) {
        float4 r0 = red[0][t], r1 = red[1][t], r2 = red[2][t], r3 = red[3][t];
        float4* op = (float4*)(out + (long)(b * Nn + j) * Dd) + t;
        float4 r = *op;
        r.x += r0.x + r1.x + r2.x + r3.x;
        r.y += r0.y + r1.y + r2.y + r3.y;
        r.z += r0.z + r1.z + r2.z + r3.z;
        r.w += r0.w + r1.w + r2.w + r3.w;
        *op = r;
    }
}

// ---------------- launch ----------------
extern "C" void kernel_launch(void* const* d_in, const int* in_sizes, int n_in,
                              void* d_out, int out_size)
{
    const float* f_b = (const float*)d_in[0];
    const float* f_w = (const float*)d_in[1];
    const float* f_s = (const float*)d_in[2];
    const float* f_m = (const float*)d_in[3];
    const float* Wq  = (const float*)d_in[4];
    const float* bq  = (const float*)d_in[5];
    const float* Wk  = (const float*)d_in[6];
    const float* bk  = (const float*)d_in[7];
    float* out = (float*)d_out;

    float* kp  = nullptr; cudaGetSymbolAddress((void**)&kp,  g_kp);
    float* up  = nullptr; cudaGetSymbolAddress((void**)&up,  g_up);
    float* fbq = nullptr; cudaGetSymbolAddress((void**)&fbq, g_fbq);
    float* S   = nullptr; cudaGetSymbolAddress((void**)&S,   g_S);
    float* Sp  = nullptr; cudaGetSymbolAddress((void**)&Sp,  g_Sp);

    cudaFuncSetAttribute(cross_attn8, cudaFuncAttributeMaxDynamicSharedMemorySize, CROSS_SMEM);

    // 1) kp[s] = f_w @ Wk^T (chunk s)   [4][80,512]
    {
        dim3 grid(Dd / 32, (Bb * Ll) / 16, FSK);
        gemm_nt_sk<<<grid, 128>>>(f_w, Wk, kp);
    }
    // 2) up[s] = (sum kp + bk) @ Wq (chunk s)
    {
        dim3 grid(Dd / 32, (Bb * Ll) / 16, FSK);
        gemm_nn_sk<<<grid, 128>>>(kp, bk, Wq, up);
    }
    // 3) cross attention + gate -> f_bq (sums partials while staging)
    {
        dim3 grid(Nn / 8, Bb);
        cross_attn8<<<grid, 512, CROSS_SMEM>>>(up, kp, bk, bq, f_w, f_b, f_s, fbq);
    }
    // 4) S partials = split-K f_bq @ f_bq^T (KS=16)
    {
        dim3 grid(Nn / 64, Nn / 64, Bb * KS);
        s_gemm_kernel<<<grid, 256>>>(fbq, Sp);
    }
    // 5) fused reduce + softmax + fbb: writes S and out = A_b@f_b + f_b
    {
        dim3 grid(Dd / 64, Nn / 32, Bb);
        softmax_fbb_kernel<<<grid, 256>>>(Sp, f_b, S, out);
    }
    // 6) moment: out += gated moment reduction (f16x2 tanh)
    {
        dim3 grid(Nn, Bb);
        moment_kernel<<<grid, 512>>>(S, f_m, f_s, out);
    }
    (void)in_sizes; (void)n_in; (void)out_size;
}